// round 4
// baseline (speedup 1.0000x reference)
#include <cuda_runtime.h>

// Problem dims (fixed by the dataset)
#define TOK    2048   // B*S
#define DMODEL 512
#define NIN    2048
#define NPROC  1024
#define DPV    256
#define NOUT   2048
#define KIN    256
#define KPROC  128
#define KOUT   256

// Scratch (device globals — no dynamic allocation allowed)
__device__ float g_acts1[TOK * NIN];      // gelu(x @ IP^T)       16 MB
__device__ float g_Wt[NIN * NPROC];       // transpose of PIW      8 MB
__device__ int   g_sel1_idx[TOK * KIN];   // stage-1 topk indices
__device__ float g_sel1_val[TOK * KIN];   // stage-1 topk values
__device__ float g_agg[TOK * DPV];        // stage-2 aggregated values
__device__ float g_acts3[TOK * NOUT];     // gelu(agg @ OIW^T)    16 MB

// ---------------------------------------------------------------------------
// XLA's f32 erf: clamp to [-4,4], rational polynomial x*P(x^2)/Q(x^2).
// Constants match xla/client/lib/math.cc ErfImpl32 / chlo erf legalization
// (what jax.lax.erf actually executes). FMA chain mirrors XLA's codegen.
// ---------------------------------------------------------------------------
__device__ __forceinline__ float erf_xla(float x) {
    x = fminf(fmaxf(x, -4.0f), 4.0f);
    float x2 = x * x;
    float p = fmaf(x2, 0.00022905065861350646f, 0.0034082910107109506f);
    p = fmaf(x2, p, 0.050955695062380861f);
    p = fmaf(x2, p, 0.18520832239976145f);
    p = fmaf(x2, p, 1.128379143519084f);
    p = x * p;
    float q = fmaf(x2, -1.1791602954361697e-7f, 2.3547966471313185e-05f);
    q = fmaf(x2, q, 0.0010179625278914885f);
    q = fmaf(x2, q, 0.014070470171167667f);
    q = fmaf(x2, q, 0.11098505178285362f);
    q = fmaf(x2, q, 0.49746925110067538f);
    q = fmaf(x2, q, 1.0f);
    return __fdiv_rn(p, q);
}

// jax.nn.gelu(approximate=False): (x * (erf(x / sqrt2) + 1)) / 2
// Division is IEEE (matches XLA's fdiv of the fp32 sqrt(2) constant).
__device__ __forceinline__ float gelu_f(float x) {
    float t = __fdiv_rn(x, 1.41421356237309504880f);  // fp32 const 0x3FB504F3
    float e = erf_xla(t);
    return x * (e + 1.0f) * 0.5f;
}

// order-preserving float -> uint key (larger float => larger key)
__device__ __forceinline__ unsigned fkey(float f) {
    unsigned b = __float_as_uint(f);
    return b ^ ((b & 0x80000000u) ? 0xFFFFFFFFu : 0x80000000u);
}

// ---------------------------------------------------------------------------
// Exact top-k for one row held in shared memory. Block = 256 threads.
// Matches jax.lax.top_k set semantics (lowest index wins among equal values).
// Slots come out in ascending-index order; caller sorts if it needs jax's
// descending-value output order. n must be a multiple of 256.
// ---------------------------------------------------------------------------
__device__ void topk_block256(const float* sdata, int n, int k,
                              int* out_idx, float* out_val)
{
    __shared__ unsigned s_cnt[256];
    __shared__ unsigned s_bin;
    __shared__ unsigned s_kneed;
    const int tid  = threadIdx.x;
    const int epb  = n >> 8;        // elements per thread (contiguous segment)
    const int base = tid * epb;

    if (tid == 0) s_kneed = (unsigned)k;
    unsigned prefix = 0;
    __syncthreads();

    // 4-pass MSB radix select: find exact bit pattern of the k-th largest key
    #pragma unroll
    for (int pass = 0; pass < 4; ++pass) {
        const int shift = 24 - 8 * pass;
        s_cnt[tid] = 0;
        __syncthreads();
        for (int e = 0; e < epb; ++e) {
            unsigned key = fkey(sdata[base + e]);
            bool match;
            if (pass == 0) match = true;
            else           match = ((key >> (shift + 8)) == prefix);
            if (match) atomicAdd(&s_cnt[(key >> shift) & 255u], 1u);
        }
        __syncthreads();
        // inclusive suffix scan of histogram
        unsigned xs = s_cnt[tid];
        for (int off = 1; off < 256; off <<= 1) {
            unsigned add = (tid + off < 256) ? s_cnt[tid + off] : 0u;
            __syncthreads();
            xs += add;
            s_cnt[tid] = xs;
            __syncthreads();
        }
        unsigned kneed = s_kneed;
        unsigned s_me  = s_cnt[tid];
        unsigned s_nx  = (tid < 255) ? s_cnt[tid + 1] : 0u;
        __syncthreads();
        if (s_me >= kneed && s_nx < kneed) {
            s_bin   = (unsigned)tid;
            s_kneed = kneed - s_nx;
        }
        __syncthreads();
        prefix = (prefix << 8) | s_bin;
    }
    const unsigned thr = prefix;           // exact key of k-th largest
    const unsigned r   = s_kneed;          // # of ==thr elements to keep

    unsigned ceq = 0, cgt = 0;
    for (int e = 0; e < epb; ++e) {
        unsigned key = fkey(sdata[base + e]);
        if (key > thr) cgt++;
        else if (key == thr) ceq++;
    }
    __syncthreads();
    s_cnt[tid] = ceq;
    __syncthreads();
    unsigned xe = s_cnt[tid];
    for (int off = 1; off < 256; off <<= 1) {
        unsigned add = (tid >= off) ? s_cnt[tid - off] : 0u;
        __syncthreads();
        xe += add;
        s_cnt[tid] = xe;
        __syncthreads();
    }
    unsigned eq_base = xe - ceq;

    unsigned eq_keep = (eq_base < r) ? min(r - eq_base, ceq) : 0u;
    unsigned ckeep   = cgt + eq_keep;
    __syncthreads();
    s_cnt[tid] = ckeep;
    __syncthreads();
    unsigned xk = s_cnt[tid];
    for (int off = 1; off < 256; off <<= 1) {
        unsigned add = (tid >= off) ? s_cnt[tid - off] : 0u;
        __syncthreads();
        xk += add;
        s_cnt[tid] = xk;
        __syncthreads();
    }
    unsigned slot = xk - ckeep;

    unsigned eqo = eq_base;
    for (int e = 0; e < epb; ++e) {
        float    f   = sdata[base + e];
        unsigned key = fkey(f);
        bool keep = false;
        if (key > thr) keep = true;
        else if (key == thr) { keep = (eqo < r); eqo++; }
        if (keep) { out_idx[slot] = base + e; out_val[slot] = f; slot++; }
    }
    __syncthreads();
}

// ---------------------------------------------------------------------------
// Bitonic sort of (val,idx) pairs, length L (power of 2 <= 256), 256 threads.
// Final order: descending value; ties -> ascending index (jax top_k order).
// ---------------------------------------------------------------------------
__device__ void sort_desc(float* v, int* idx, int L) {
    const int tid = threadIdx.x;
    for (int size = 2; size <= L; size <<= 1) {
        for (int stride = size >> 1; stride > 0; stride >>= 1) {
            __syncthreads();
            for (int i = tid; i < (L >> 1); i += 256) {
                int lo = 2 * i - (i & (stride - 1));
                int hi = lo + stride;
                float va = v[lo], vb = v[hi];
                int   ia = idx[lo], ib = idx[hi];
                bool aBeforeB = (va > vb) || (va == vb && ia < ib);
                bool dirDesc  = ((lo & size) == 0);
                if (dirDesc ? !aBeforeB : aBeforeB) {
                    v[lo] = vb; v[hi] = va;
                    idx[lo] = ib; idx[hi] = ia;
                }
            }
        }
    }
    __syncthreads();
}

// ---------------------------------------------------------------------------
// SGEMM: C[M,N] = gelu(A[M,K] * B[N,K]^T), row-major, fp32, sequential
// ascending-K FMA accumulation (matches cublas SIMT sgemm / Eigen gebp order).
// 128x128 tile, BK=8, 256 threads, 8x8 microtile, double-buffered smem.
// ---------------------------------------------------------------------------
template <int K>
__device__ __forceinline__ void sgemm_gelu_body(
    const float* __restrict__ A, const float* __restrict__ B,
    float* __restrict__ C, int N)
{
    constexpr int BK = 8, LDA = 132;
    __shared__ float sA[2][BK * LDA];
    __shared__ float sB[2][BK * LDA];
    const int tid = threadIdx.x;
    const int tx  = tid & 15, ty = tid >> 4;
    const int m0  = blockIdx.y * 128;
    const int n0  = blockIdx.x * 128;
    const int lrow = tid >> 1;
    const int lcol = (tid & 1) << 2;

    const float* Ag = A + (size_t)(m0 + lrow) * K + lcol;
    const float* Bg = B + (size_t)(n0 + lrow) * K + lcol;

    float acc[8][8];
    #pragma unroll
    for (int i = 0; i < 8; ++i)
        #pragma unroll
        for (int j = 0; j < 8; ++j) acc[i][j] = 0.f;

    {   // preload tile 0
        float4 a = *(const float4*)Ag;
        float4 b = *(const float4*)Bg;
        sA[0][(lcol+0)*LDA+lrow]=a.x; sA[0][(lcol+1)*LDA+lrow]=a.y;
        sA[0][(lcol+2)*LDA+lrow]=a.z; sA[0][(lcol+3)*LDA+lrow]=a.w;
        sB[0][(lcol+0)*LDA+lrow]=b.x; sB[0][(lcol+1)*LDA+lrow]=b.y;
        sB[0][(lcol+2)*LDA+lrow]=b.z; sB[0][(lcol+3)*LDA+lrow]=b.w;
    }
    __syncthreads();

    constexpr int NT = K / BK;
    int cur = 0;
    for (int kt = 0; kt < NT; ++kt) {
        float4 an, bn;
        if (kt + 1 < NT) {
            an = *(const float4*)(Ag + (kt + 1) * BK);
            bn = *(const float4*)(Bg + (kt + 1) * BK);
        }
        #pragma unroll
        for (int kk = 0; kk < BK; ++kk) {
            float4 a0 = *(const float4*)&sA[cur][kk*LDA + ty*8];
            float4 a1 = *(const float4*)&sA[cur][kk*LDA + ty*8 + 4];
            float4 b0 = *(const float4*)&sB[cur][kk*LDA + tx*8];
            float4 b1 = *(const float4*)&sB[cur][kk*LDA + tx*8 + 4];
            float ar[8] = {a0.x,a0.y,a0.z,a0.w,a1.x,a1.y,a1.z,a1.w};
            float br[8] = {b0.x,b0.y,b0.z,b0.w,b1.x,b1.y,b1.z,b1.w};
            #pragma unroll
            for (int i = 0; i < 8; ++i)
                #pragma unroll
                for (int j = 0; j < 8; ++j)
                    acc[i][j] = fmaf(ar[i], br[j], acc[i][j]);
        }
        if (kt + 1 < NT) {
            int nxt = cur ^ 1;
            sA[nxt][(lcol+0)*LDA+lrow]=an.x; sA[nxt][(lcol+1)*LDA+lrow]=an.y;
            sA[nxt][(lcol+2)*LDA+lrow]=an.z; sA[nxt][(lcol+3)*LDA+lrow]=an.w;
            sB[nxt][(lcol+0)*LDA+lrow]=bn.x; sB[nxt][(lcol+1)*LDA+lrow]=bn.y;
            sB[nxt][(lcol+2)*LDA+lrow]=bn.z; sB[nxt][(lcol+3)*LDA+lrow]=bn.w;
            cur = nxt;
        }
        __syncthreads();
    }

    #pragma unroll
    for (int i = 0; i < 8; ++i) {
        float* Cr = C + (size_t)(m0 + ty*8 + i) * N + n0 + tx*8;
        float4 o0, o1;
        o0.x = gelu_f(acc[i][0]); o0.y = gelu_f(acc[i][1]);
        o0.z = gelu_f(acc[i][2]); o0.w = gelu_f(acc[i][3]);
        o1.x = gelu_f(acc[i][4]); o1.y = gelu_f(acc[i][5]);
        o1.z = gelu_f(acc[i][6]); o1.w = gelu_f(acc[i][7]);
        *(float4*)Cr       = o0;
        *(float4*)(Cr + 4) = o1;
    }
}

__global__ __launch_bounds__(256) void k_gemm1(const float* __restrict__ x,
                                               const float* __restrict__ ip) {
    sgemm_gelu_body<DMODEL>(x, ip, g_acts1, NIN);
}
__global__ __launch_bounds__(256) void k_gemm3(const float* __restrict__ oiw) {
    sgemm_gelu_body<DPV>(g_agg, oiw, g_acts3, NOUT);
}

// Transpose process_input_weights [NPROC, NIN] -> g_Wt [NIN, NPROC]
__global__ void k_transpose(const float* __restrict__ W) {
    __shared__ float tile[32][33];
    int x  = blockIdx.x * 32 + threadIdx.x;   // n_in index
    int y0 = blockIdx.y * 32;                 // proc index base
    #pragma unroll
    for (int j = 0; j < 32; j += 8)
        tile[threadIdx.y + j][threadIdx.x] = W[(size_t)(y0 + threadIdx.y + j) * NIN + x];
    __syncthreads();
    int px  = y0 + threadIdx.x;               // proc
    int iy0 = blockIdx.x * 32;                // n_in
    #pragma unroll
    for (int j = 0; j < 32; j += 8)
        g_Wt[(size_t)(iy0 + threadIdx.y + j) * NPROC + px] = tile[threadIdx.x][threadIdx.y + j];
}

// Stage 1 top-k: per token, top-256 of 2048 gelu activations.
// Stored in ascending-index order: the downstream use is a dense scatter +
// ascending-n contraction, so index order == reference's accumulation order.
__global__ __launch_bounds__(256) void k_top1() {
    __shared__ float sdata[NIN];
    __shared__ int   sidx[KIN];
    __shared__ float sval[KIN];
    const int t   = blockIdx.x;
    const int tid = threadIdx.x;
    const float* row = g_acts1 + (size_t)t * NIN;
    for (int i = tid; i < NIN; i += 256) sdata[i] = row[i];
    __syncthreads();
    topk_block256(sdata, NIN, KIN, sidx, sval);
    g_sel1_idx[t * KIN + tid] = sidx[tid];
    g_sel1_val[t * KIN + tid] = sval[tid];
}

// Stage 2 fused: sparse gather-GEMM (ascending-n sequential FMA == dense
// reference order) + gelu + top-128 + sort desc + softmax (sequential sum in
// jax's sorted order) + weighted value gather in sorted order.
__global__ __launch_bounds__(256) void k_stage2(const float* __restrict__ PV) {
    __shared__ int   sIdx[KIN];
    __shared__ float sVal[KIN];
    __shared__ float sdata[NPROC];
    __shared__ int   pidx[KPROC];
    __shared__ float pval[KPROC];
    __shared__ float sexp[KPROC];
    __shared__ float sdenom;
    const int t   = blockIdx.x;
    const int tid = threadIdx.x;
    sIdx[tid] = g_sel1_idx[t * KIN + tid];
    sVal[tid] = g_sel1_val[t * KIN + tid];
    __syncthreads();

    float a0 = 0.f, a1 = 0.f, a2 = 0.f, a3 = 0.f;
    #pragma unroll 4
    for (int j = 0; j < KIN; ++j) {         // ascending n (reference order)
        const float v = sVal[j];
        const float* w = g_Wt + (size_t)sIdx[j] * NPROC + tid;
        a0 = fmaf(v, w[0],   a0);
        a1 = fmaf(v, w[256], a1);
        a2 = fmaf(v, w[512], a2);
        a3 = fmaf(v, w[768], a3);
    }
    sdata[tid]       = gelu_f(a0);
    sdata[tid + 256] = gelu_f(a1);
    sdata[tid + 512] = gelu_f(a2);
    sdata[tid + 768] = gelu_f(a3);
    __syncthreads();

    topk_block256(sdata, NPROC, KPROC, pidx, pval);
    sort_desc(pval, pidx, KPROC);           // jax top_k output order

    // softmax, jax order: max = pval[0]; sum sequentially over sorted k
    if (tid < KPROC) sexp[tid] = expf(pval[tid] - pval[0]);
    __syncthreads();
    if (tid == 0) {
        float s = 0.f;
        for (int j = 0; j < KPROC; ++j) s += sexp[j];
        sdenom = s;
    }
    __syncthreads();
    const float denom = sdenom;
    if (tid < KPROC) pval[tid] = __fdiv_rn(sexp[tid], denom);
    __syncthreads();

    // weighted value gather, sequential over sorted k (reference einsum order)
    float acc = 0.f;
    #pragma unroll 4
    for (int j = 0; j < KPROC; ++j)
        acc = fmaf(pval[j], PV[(size_t)pidx[j] * DPV + tid], acc);
    g_agg[(size_t)t * DPV + tid] = acc;
}

// Stage 3 fused: top-256 of 2048, sort desc, weighted pattern combine in
// sorted order (reference einsum order) -> out
__global__ __launch_bounds__(256) void k_stage3(const float* __restrict__ OP,
                                                float* __restrict__ out) {
    __shared__ float sdata[NOUT];
    __shared__ int   sidx[KOUT];
    __shared__ float sval[KOUT];
    const int t   = blockIdx.x;
    const int tid = threadIdx.x;
    const float* row = g_acts3 + (size_t)t * NOUT;
    for (int i = tid; i < NOUT; i += 256) sdata[i] = row[i];
    __syncthreads();
    topk_block256(sdata, NOUT, KOUT, sidx, sval);
    sort_desc(sval, sidx, KOUT);            // jax top_k output order

    float a0 = 0.f, a1 = 0.f;
    #pragma unroll 4
    for (int j = 0; j < KOUT; ++j) {        // sequential over sorted k
        const float v = sval[j];
        const float* p = OP + (size_t)sidx[j] * DMODEL + tid;
        a0 = fmaf(v, p[0],   a0);
        a1 = fmaf(v, p[256], a1);
    }
    out[(size_t)t * DMODEL + tid]       = a0;
    out[(size_t)t * DMODEL + tid + 256] = a1;
}

extern "C" void kernel_launch(void* const* d_in, const int* in_sizes, int n_in,
                              void* d_out, int out_size) {
    const float* x   = (const float*)d_in[0];  // [2,1024,512]
    const float* ip  = (const float*)d_in[1];  // [2048,512]
    const float* piw = (const float*)d_in[2];  // [1024,2048]
    const float* pv  = (const float*)d_in[3];  // [1024,256]
    const float* oiw = (const float*)d_in[4];  // [2048,256]
    const float* op  = (const float*)d_in[5];  // [2048,512]
    float* out = (float*)d_out;                // [2,1024,512]

    k_transpose<<<dim3(NIN / 32, NPROC / 32), dim3(32, 8)>>>(piw);
    k_gemm1<<<dim3(NIN / 128, TOK / 128), 256>>>(x, ip);
    k_top1<<<TOK, 256>>>();
    k_stage2<<<TOK, 256>>>(pv);
    k_gemm3<<<dim3(NOUT / 128, TOK / 128), 256>>>(oiw);
    k_stage3<<<TOK, 256>>>(op, out);
}

// round 5
// speedup vs baseline: 1.0785x; 1.0785x over previous
#include <cuda_runtime.h>

// Problem dims (fixed by the dataset)
#define TOK    2048   // B*S
#define DMODEL 512
#define NIN    2048
#define NPROC  1024
#define DPV    256
#define NOUT   2048
#define KIN    256
#define KPROC  128
#define KOUT   256

// Scratch (device globals — no dynamic allocation allowed)
__device__ float g_acts1[TOK * NIN];      // gelu(x @ IP^T)       16 MB
__device__ float g_Wt[NIN * NPROC];       // transpose of PIW      8 MB
__device__ float g_agg[TOK * DPV];        // stage-2 aggregated values
__device__ float g_acts3[TOK * NOUT];     // gelu(agg @ OIW^T)    16 MB

// ---------------------------------------------------------------------------
// XLA's f32 erf: clamp to [-4,4], rational polynomial x*P(x^2)/Q(x^2).
// Constants match xla/client/lib/math.cc ErfImpl32 (what jax.lax.erf runs).
// ---------------------------------------------------------------------------
__device__ __forceinline__ float erf_xla(float x) {
    x = fminf(fmaxf(x, -4.0f), 4.0f);
    float x2 = x * x;
    float p = fmaf(x2, 0.00022905065861350646f, 0.0034082910107109506f);
    p = fmaf(x2, p, 0.050955695062380861f);
    p = fmaf(x2, p, 0.18520832239976145f);
    p = fmaf(x2, p, 1.128379143519084f);
    p = x * p;
    float q = fmaf(x2, -1.1791602954361697e-7f, 2.3547966471313185e-05f);
    q = fmaf(x2, q, 0.0010179625278914885f);
    q = fmaf(x2, q, 0.014070470171167667f);
    q = fmaf(x2, q, 0.11098505178285362f);
    q = fmaf(x2, q, 0.49746925110067538f);
    q = fmaf(x2, q, 1.0f);
    return __fdiv_rn(p, q);
}

// jax.nn.gelu(approximate=False): (x * (erf(x / sqrt2) + 1)) / 2
__device__ __forceinline__ float gelu_f(float x) {
    float t = __fdiv_rn(x, 1.41421356237309504880f);
    float e = erf_xla(t);
    return x * (e + 1.0f) * 0.5f;
}

// order-preserving float -> uint key (larger float => larger key)
__device__ __forceinline__ unsigned fkey(float f) {
    unsigned b = __float_as_uint(f);
    return b ^ ((b & 0x80000000u) ? 0xFFFFFFFFu : 0x80000000u);
}

// ---------------------------------------------------------------------------
// Warp-shuffle scan primitives
// ---------------------------------------------------------------------------
__device__ __forceinline__ unsigned warp_suffix_incl(unsigned v, int lane) {
    #pragma unroll
    for (int off = 1; off < 32; off <<= 1) {
        unsigned o = __shfl_down_sync(0xffffffffu, v, off);
        if (lane + off < 32) v += o;
    }
    return v;
}
__device__ __forceinline__ unsigned warp_prefix_incl(unsigned v, int lane) {
    #pragma unroll
    for (int off = 1; off < 32; off <<= 1) {
        unsigned o = __shfl_up_sync(0xffffffffu, v, off);
        if (lane >= off) v += o;
    }
    return v;
}

// block-wide (256 thr) exclusive prefix sum; s_wsum is 8-entry scratch
__device__ __forceinline__ unsigned block_prefix_excl(unsigned x, unsigned* s_wsum) {
    const int tid = threadIdx.x, lane = tid & 31, wid = tid >> 5;
    unsigned v = warp_prefix_incl(x, lane);
    __syncthreads();                       // scratch free
    if (lane == 31) s_wsum[wid] = v;
    __syncthreads();
    unsigned add = 0;
    #pragma unroll
    for (int w = 0; w < 8; ++w) if (w < wid) add += s_wsum[w];
    return v + add - x;
}

// ---------------------------------------------------------------------------
// Exact top-k for one row in shared memory. Block = 256 threads.
// Same selection + slot-order semantics as the R4 version (jax.lax.top_k set,
// lowest index wins ties; slots in ascending-index order), but with register-
// resident keys and warp-shuffle scans (~22 bars instead of ~100).
// n = EPB*256.
// ---------------------------------------------------------------------------
template <int EPB>
__device__ void topk_fast(const float* sdata, int k, int* out_idx, float* out_val)
{
    __shared__ unsigned s_cnt[256];
    __shared__ unsigned s_wsum[8];
    __shared__ unsigned s_bin;
    __shared__ unsigned s_kneed;
    const int tid  = threadIdx.x, lane = tid & 31, wid = tid >> 5;
    const int base = tid * EPB;

    unsigned key[EPB];
    #pragma unroll
    for (int e = 0; e < EPB; ++e) key[e] = fkey(sdata[base + e]);

    if (tid == 0) s_kneed = (unsigned)k;
    unsigned prefix = 0;

    #pragma unroll
    for (int pass = 0; pass < 4; ++pass) {
        const int shift = 24 - 8 * pass;
        s_cnt[tid] = 0;
        __syncthreads();
        #pragma unroll
        for (int e = 0; e < EPB; ++e) {
            bool m;
            if (pass == 0) m = true;
            else           m = ((key[e] >> (shift + 8)) == prefix);
            if (m) atomicAdd(&s_cnt[(key[e] >> shift) & 255u], 1u);
        }
        __syncthreads();
        unsigned own = s_cnt[tid];
        unsigned v   = warp_suffix_incl(own, lane);   // lane0 = warp total
        if (lane == 0) s_wsum[wid] = v;
        __syncthreads();
        unsigned add = 0;
        #pragma unroll
        for (int w = 0; w < 8; ++w) if (w > wid) add += s_wsum[w];
        v += add;                                     // inclusive suffix over 256 bins
        unsigned kneed = s_kneed;
        __syncthreads();
        if (v >= kneed && (v - own) < kneed) {
            s_bin   = (unsigned)tid;
            s_kneed = kneed - (v - own);
        }
        __syncthreads();
        prefix = (prefix << 8) | s_bin;
    }
    const unsigned thr = prefix;           // exact key of k-th largest
    const unsigned r   = s_kneed;          // # of ==thr elements to keep

    unsigned ceq = 0, cgt = 0;
    #pragma unroll
    for (int e = 0; e < EPB; ++e) {
        if (key[e] > thr) cgt++;
        else if (key[e] == thr) ceq++;
    }
    unsigned eq_base = block_prefix_excl(ceq, s_wsum);
    unsigned eq_keep = (eq_base < r) ? min(r - eq_base, ceq) : 0u;
    unsigned slot    = block_prefix_excl(cgt + eq_keep, s_wsum);

    unsigned eqo = eq_base;
    #pragma unroll
    for (int e = 0; e < EPB; ++e) {
        bool keep = false;
        if (key[e] > thr) keep = true;
        else if (key[e] == thr) { keep = (eqo < r); eqo++; }
        if (keep) { out_idx[slot] = base + e; out_val[slot] = sdata[base + e]; slot++; }
    }
    __syncthreads();
}

// ---------------------------------------------------------------------------
// Bitonic sort of (val,idx) pairs, length L (power of 2 <= 256), 256 threads.
// Final order: descending value; ties -> ascending index (jax top_k order).
// ---------------------------------------------------------------------------
__device__ void sort_desc(float* v, int* idx, int L) {
    const int tid = threadIdx.x;
    for (int size = 2; size <= L; size <<= 1) {
        for (int stride = size >> 1; stride > 0; stride >>= 1) {
            __syncthreads();
            for (int i = tid; i < (L >> 1); i += 256) {
                int lo = 2 * i - (i & (stride - 1));
                int hi = lo + stride;
                float va = v[lo], vb = v[hi];
                int   ia = idx[lo], ib = idx[hi];
                bool aBeforeB = (va > vb) || (va == vb && ia < ib);
                bool dirDesc  = ((lo & size) == 0);
                if (dirDesc ? !aBeforeB : aBeforeB) {
                    v[lo] = vb; v[hi] = va;
                    idx[lo] = ib; idx[hi] = ia;
                }
            }
        }
    }
    __syncthreads();
}

// ---------------------------------------------------------------------------
// SGEMM: C[M,N] = gelu(A[M,K] * B[N,K]^T), row-major, fp32, sequential
// ascending-K FMA accumulation. Bitwise identical to the R4 (passing) version.
// 128x128 tile, BK=8, 256 threads, 8x8 microtile, double-buffered smem.
// ---------------------------------------------------------------------------
template <int K>
__device__ __forceinline__ void sgemm_gelu_body(
    const float* __restrict__ A, const float* __restrict__ B,
    float* __restrict__ C, int N)
{
    constexpr int BK = 8, LDA = 132;
    __shared__ float sA[2][BK * LDA];
    __shared__ float sB[2][BK * LDA];
    const int tid = threadIdx.x;
    const int tx  = tid & 15, ty = tid >> 4;
    const int m0  = blockIdx.y * 128;
    const int n0  = blockIdx.x * 128;
    const int lrow = tid >> 1;
    const int lcol = (tid & 1) << 2;

    const float* Ag = A + (size_t)(m0 + lrow) * K + lcol;
    const float* Bg = B + (size_t)(n0 + lrow) * K + lcol;

    float acc[8][8];
    #pragma unroll
    for (int i = 0; i < 8; ++i)
        #pragma unroll
        for (int j = 0; j < 8; ++j) acc[i][j] = 0.f;

    {   // preload tile 0
        float4 a = *(const float4*)Ag;
        float4 b = *(const float4*)Bg;
        sA[0][(lcol+0)*LDA+lrow]=a.x; sA[0][(lcol+1)*LDA+lrow]=a.y;
        sA[0][(lcol+2)*LDA+lrow]=a.z; sA[0][(lcol+3)*LDA+lrow]=a.w;
        sB[0][(lcol+0)*LDA+lrow]=b.x; sB[0][(lcol+1)*LDA+lrow]=b.y;
        sB[0][(lcol+2)*LDA+lrow]=b.z; sB[0][(lcol+3)*LDA+lrow]=b.w;
    }
    __syncthreads();

    constexpr int NT = K / BK;
    int cur = 0;
    for (int kt = 0; kt < NT; ++kt) {
        float4 an, bn;
        if (kt + 1 < NT) {
            an = *(const float4*)(Ag + (kt + 1) * BK);
            bn = *(const float4*)(Bg + (kt + 1) * BK);
        }
        #pragma unroll
        for (int kk = 0; kk < BK; ++kk) {
            float4 a0 = *(const float4*)&sA[cur][kk*LDA + ty*8];
            float4 a1 = *(const float4*)&sA[cur][kk*LDA + ty*8 + 4];
            float4 b0 = *(const float4*)&sB[cur][kk*LDA + tx*8];
            float4 b1 = *(const float4*)&sB[cur][kk*LDA + tx*8 + 4];
            float ar[8] = {a0.x,a0.y,a0.z,a0.w,a1.x,a1.y,a1.z,a1.w};
            float br[8] = {b0.x,b0.y,b0.z,b0.w,b1.x,b1.y,b1.z,b1.w};
            #pragma unroll
            for (int i = 0; i < 8; ++i)
                #pragma unroll
                for (int j = 0; j < 8; ++j)
                    acc[i][j] = fmaf(ar[i], br[j], acc[i][j]);
        }
        if (kt + 1 < NT) {
            int nxt = cur ^ 1;
            sA[nxt][(lcol+0)*LDA+lrow]=an.x; sA[nxt][(lcol+1)*LDA+lrow]=an.y;
            sA[nxt][(lcol+2)*LDA+lrow]=an.z; sA[nxt][(lcol+3)*LDA+lrow]=an.w;
            sB[nxt][(lcol+0)*LDA+lrow]=bn.x; sB[nxt][(lcol+1)*LDA+lrow]=bn.y;
            sB[nxt][(lcol+2)*LDA+lrow]=bn.z; sB[nxt][(lcol+3)*LDA+lrow]=bn.w;
            cur = nxt;
        }
        __syncthreads();
    }

    #pragma unroll
    for (int i = 0; i < 8; ++i) {
        float* Cr = C + (size_t)(m0 + ty*8 + i) * N + n0 + tx*8;
        float4 o0, o1;
        o0.x = gelu_f(acc[i][0]); o0.y = gelu_f(acc[i][1]);
        o0.z = gelu_f(acc[i][2]); o0.w = gelu_f(acc[i][3]);
        o1.x = gelu_f(acc[i][4]); o1.y = gelu_f(acc[i][5]);
        o1.z = gelu_f(acc[i][6]); o1.w = gelu_f(acc[i][7]);
        *(float4*)Cr       = o0;
        *(float4*)(Cr + 4) = o1;
    }
}

__global__ __launch_bounds__(256) void k_gemm1(const float* __restrict__ x,
                                               const float* __restrict__ ip) {
    sgemm_gelu_body<DMODEL>(x, ip, g_acts1, NIN);
}
__global__ __launch_bounds__(256) void k_gemm3(const float* __restrict__ oiw) {
    sgemm_gelu_body<DPV>(g_agg, oiw, g_acts3, NOUT);
}

// Transpose process_input_weights [NPROC, NIN] -> g_Wt [NIN, NPROC]
__global__ void k_transpose(const float* __restrict__ W) {
    __shared__ float tile[32][33];
    int x  = blockIdx.x * 32 + threadIdx.x;   // n_in index
    int y0 = blockIdx.y * 32;                 // proc index base
    #pragma unroll
    for (int j = 0; j < 32; j += 8)
        tile[threadIdx.y + j][threadIdx.x] = W[(size_t)(y0 + threadIdx.y + j) * NIN + x];
    __syncthreads();
    int px  = y0 + threadIdx.x;               // proc
    int iy0 = blockIdx.x * 32;                // n_in
    #pragma unroll
    for (int j = 0; j < 32; j += 8)
        g_Wt[(size_t)(iy0 + threadIdx.y + j) * NPROC + px] = tile[threadIdx.x][threadIdx.y + j];
}

// ---------------------------------------------------------------------------
// Stage 1+2 fused: load acts1 row -> top-256 (ascending-index slots) ->
// sparse gather-GEMM (ascending-n sequential FMA, identical order to R4) ->
// gelu -> top-128 -> sort desc -> softmax (sequential, jax order) ->
// weighted value gather in sorted order -> g_agg.
// ---------------------------------------------------------------------------
__global__ __launch_bounds__(256) void k_stage2(const float* __restrict__ PV) {
    __shared__ float sdata[NIN];        // acts1 row (2048), then proc acts (1024)
    __shared__ int   sIdx[KIN];
    __shared__ float sVal[KIN];
    __shared__ int   pidx[KPROC];
    __shared__ float pval[KPROC];
    __shared__ float sexp[KPROC];
    __shared__ float sdenom;
    const int t   = blockIdx.x;
    const int tid = threadIdx.x;

    {   // load acts1 row (vectorized, 8 floats per thread)
        const float4* row = (const float4*)(g_acts1 + (size_t)t * NIN);
        float4 r0 = row[tid];
        float4 r1 = row[tid + 256];
        ((float4*)sdata)[tid]       = r0;
        ((float4*)sdata)[tid + 256] = r1;
    }
    __syncthreads();

    topk_fast<NIN / 256>(sdata, KIN, sIdx, sVal);   // stage-1 selection

    float a0 = 0.f, a1 = 0.f, a2 = 0.f, a3 = 0.f;
    #pragma unroll 8
    for (int j = 0; j < KIN; ++j) {         // ascending n (reference order)
        const float v = sVal[j];
        const float* w = g_Wt + (size_t)sIdx[j] * NPROC + tid;
        a0 = fmaf(v, w[0],   a0);
        a1 = fmaf(v, w[256], a1);
        a2 = fmaf(v, w[512], a2);
        a3 = fmaf(v, w[768], a3);
    }
    __syncthreads();                        // done reading sdata (topk ended w/ sync, but
                                            // ensure all threads finished matmul reads of sIdx/sVal
                                            // before any reuse; sdata overwrite below)
    sdata[tid]       = gelu_f(a0);
    sdata[tid + 256] = gelu_f(a1);
    sdata[tid + 512] = gelu_f(a2);
    sdata[tid + 768] = gelu_f(a3);
    __syncthreads();

    topk_fast<NPROC / 256>(sdata, KPROC, pidx, pval);
    sort_desc(pval, pidx, KPROC);           // jax top_k output order

    // softmax, jax order: max = pval[0]; sum sequentially over sorted k
    if (tid < KPROC) sexp[tid] = expf(pval[tid] - pval[0]);
    __syncthreads();
    if (tid == 0) {
        float s = 0.f;
        for (int j = 0; j < KPROC; ++j) s += sexp[j];
        sdenom = s;
    }
    __syncthreads();
    const float denom = sdenom;
    if (tid < KPROC) pval[tid] = __fdiv_rn(sexp[tid], denom);
    __syncthreads();

    // weighted value gather, sequential over sorted k (reference einsum order)
    float acc = 0.f;
    #pragma unroll 8
    for (int j = 0; j < KPROC; ++j)
        acc = fmaf(pval[j], PV[(size_t)pidx[j] * DPV + tid], acc);
    g_agg[(size_t)t * DPV + tid] = acc;
}

// Stage 3 fused: top-256 of 2048, sort desc, weighted pattern combine in
// sorted order (reference einsum order) -> out
__global__ __launch_bounds__(256) void k_stage3(const float* __restrict__ OP,
                                                float* __restrict__ out) {
    __shared__ float sdata[NOUT];
    __shared__ int   sidx[KOUT];
    __shared__ float sval[KOUT];
    const int t   = blockIdx.x;
    const int tid = threadIdx.x;
    {
        const float4* row = (const float4*)(g_acts3 + (size_t)t * NOUT);
        float4 r0 = row[tid];
        float4 r1 = row[tid + 256];
        ((float4*)sdata)[tid]       = r0;
        ((float4*)sdata)[tid + 256] = r1;
    }
    __syncthreads();
    topk_fast<NOUT / 256>(sdata, KOUT, sidx, sval);
    sort_desc(sval, sidx, KOUT);            // jax top_k output order

    float a0 = 0.f, a1 = 0.f;
    #pragma unroll 8
    for (int j = 0; j < KOUT; ++j) {        // sequential over sorted k
        const float v = sval[j];
        const float* p = OP + (size_t)sidx[j] * DMODEL + tid;
        a0 = fmaf(v, p[0],   a0);
        a1 = fmaf(v, p[256], a1);
    }
    out[(size_t)t * DMODEL + tid]       = a0;
    out[(size_t)t * DMODEL + tid + 256] = a1;
}

extern "C" void kernel_launch(void* const* d_in, const int* in_sizes, int n_in,
                              void* d_out, int out_size) {
    const float* x   = (const float*)d_in[0];  // [2,1024,512]
    const float* ip  = (const float*)d_in[1];  // [2048,512]
    const float* piw = (const float*)d_in[2];  // [1024,2048]
    const float* pv  = (const float*)d_in[3];  // [1024,256]
    const float* oiw = (const float*)d_in[4];  // [2048,256]
    const float* op  = (const float*)d_in[5];  // [2048,512]
    float* out = (float*)d_out;                // [2,1024,512]

    k_transpose<<<dim3(NIN / 32, NPROC / 32), dim3(32, 8)>>>(piw);
    k_gemm1<<<dim3(NIN / 128, TOK / 128), 256>>>(x, ip);
    k_stage2<<<TOK, 256>>>(pv);
    k_gemm3<<<dim3(NOUT / 128, TOK / 128), 256>>>(oiw);
    k_stage3<<<TOK, 256>>>(op, out);
}

// round 6
// speedup vs baseline: 1.0873x; 1.0082x over previous
#include <cuda_runtime.h>

// Problem dims (fixed by the dataset)
#define TOK    2048   // B*S
#define DMODEL 512
#define NIN    2048
#define NPROC  1024
#define DPV    256
#define NOUT   2048
#define KIN    256
#define KPROC  128
#define KOUT   256

// Scratch (device globals — no dynamic allocation allowed)
__device__ float g_acts1[TOK * NIN];      // gelu(x @ IP^T)       16 MB
__device__ float g_Wt[NIN * NPROC];       // transpose of PIW      8 MB
__device__ float g_agg[TOK * DPV];        // stage-2 aggregated values
__device__ float g_acts3[TOK * NOUT];     // gelu(agg @ OIW^T)    16 MB

// ---------------------------------------------------------------------------
// XLA's f32 erf: clamp to [-4,4], rational polynomial x*P(x^2)/Q(x^2).
// Constants match xla/client/lib/math.cc ErfImpl32 (what jax.lax.erf runs).
// ---------------------------------------------------------------------------
__device__ __forceinline__ float erf_xla(float x) {
    x = fminf(fmaxf(x, -4.0f), 4.0f);
    float x2 = x * x;
    float p = fmaf(x2, 0.00022905065861350646f, 0.0034082910107109506f);
    p = fmaf(x2, p, 0.050955695062380861f);
    p = fmaf(x2, p, 0.18520832239976145f);
    p = fmaf(x2, p, 1.128379143519084f);
    p = x * p;
    float q = fmaf(x2, -1.1791602954361697e-7f, 2.3547966471313185e-05f);
    q = fmaf(x2, q, 0.0010179625278914885f);
    q = fmaf(x2, q, 0.014070470171167667f);
    q = fmaf(x2, q, 0.11098505178285362f);
    q = fmaf(x2, q, 0.49746925110067538f);
    q = fmaf(x2, q, 1.0f);
    return __fdiv_rn(p, q);
}

// jax.nn.gelu(approximate=False): (x * (erf(x / sqrt2) + 1)) / 2
__device__ __forceinline__ float gelu_f(float x) {
    float t = __fdiv_rn(x, 1.41421356237309504880f);
    float e = erf_xla(t);
    return x * (e + 1.0f) * 0.5f;
}

// order-preserving float -> uint key (larger float => larger key)
__device__ __forceinline__ unsigned fkey(float f) {
    unsigned b = __float_as_uint(f);
    return b ^ ((b & 0x80000000u) ? 0xFFFFFFFFu : 0x80000000u);
}

// ---------------------------------------------------------------------------
// Packed f32x2 helpers (sm_103a). Each half is an independent IEEE rn FMA,
// bitwise identical to scalar fmaf on that half.
// ---------------------------------------------------------------------------
__device__ __forceinline__ void ffma2(unsigned long long& d,
                                      unsigned long long a,
                                      unsigned long long b) {
    asm("fma.rn.f32x2 %0, %1, %2, %0;" : "+l"(d) : "l"(a), "l"(b));
}
__device__ __forceinline__ unsigned long long dup2(float x) {
    unsigned long long r;
    asm("mov.b64 %0, {%1, %1};" : "=l"(r) : "f"(x));
    return r;
}
__device__ __forceinline__ float2 unpack2(unsigned long long v) {
    float2 f;
    asm("mov.b64 {%0, %1}, %2;" : "=f"(f.x), "=f"(f.y) : "l"(v));
    return f;
}

// ---------------------------------------------------------------------------
// Warp-shuffle scan primitives
// ---------------------------------------------------------------------------
__device__ __forceinline__ unsigned warp_suffix_incl(unsigned v, int lane) {
    #pragma unroll
    for (int off = 1; off < 32; off <<= 1) {
        unsigned o = __shfl_down_sync(0xffffffffu, v, off);
        if (lane + off < 32) v += o;
    }
    return v;
}
__device__ __forceinline__ unsigned warp_prefix_incl(unsigned v, int lane) {
    #pragma unroll
    for (int off = 1; off < 32; off <<= 1) {
        unsigned o = __shfl_up_sync(0xffffffffu, v, off);
        if (lane >= off) v += o;
    }
    return v;
}

// block-wide (256 thr) exclusive prefix sum; s_wsum is 8-entry scratch
__device__ __forceinline__ unsigned block_prefix_excl(unsigned x, unsigned* s_wsum) {
    const int tid = threadIdx.x, lane = tid & 31, wid = tid >> 5;
    unsigned v = warp_prefix_incl(x, lane);
    __syncthreads();                       // scratch free
    if (lane == 31) s_wsum[wid] = v;
    __syncthreads();
    unsigned add = 0;
    #pragma unroll
    for (int w = 0; w < 8; ++w) if (w < wid) add += s_wsum[w];
    return v + add - x;
}

// ---------------------------------------------------------------------------
// Exact top-k for one row in shared memory. Block = 256 threads.
// jax.lax.top_k set semantics (lowest index wins ties); slots in
// ascending-index order. n = EPB*256.
// ---------------------------------------------------------------------------
template <int EPB>
__device__ void topk_fast(const float* sdata, int k, int* out_idx, float* out_val)
{
    __shared__ unsigned s_cnt[256];
    __shared__ unsigned s_wsum[8];
    __shared__ unsigned s_bin;
    __shared__ unsigned s_kneed;
    const int tid  = threadIdx.x, lane = tid & 31, wid = tid >> 5;
    const int base = tid * EPB;

    unsigned key[EPB];
    #pragma unroll
    for (int e = 0; e < EPB; ++e) key[e] = fkey(sdata[base + e]);

    if (tid == 0) s_kneed = (unsigned)k;
    unsigned prefix = 0;

    #pragma unroll
    for (int pass = 0; pass < 4; ++pass) {
        const int shift = 24 - 8 * pass;
        s_cnt[tid] = 0;
        __syncthreads();
        #pragma unroll
        for (int e = 0; e < EPB; ++e) {
            bool m;
            if (pass == 0) m = true;
            else           m = ((key[e] >> (shift + 8)) == prefix);
            if (m) atomicAdd(&s_cnt[(key[e] >> shift) & 255u], 1u);
        }
        __syncthreads();
        unsigned own = s_cnt[tid];
        unsigned v   = warp_suffix_incl(own, lane);   // lane0 = warp total
        if (lane == 0) s_wsum[wid] = v;
        __syncthreads();
        unsigned add = 0;
        #pragma unroll
        for (int w = 0; w < 8; ++w) if (w > wid) add += s_wsum[w];
        v += add;                                     // inclusive suffix over 256 bins
        unsigned kneed = s_kneed;
        __syncthreads();
        if (v >= kneed && (v - own) < kneed) {
            s_bin   = (unsigned)tid;
            s_kneed = kneed - (v - own);
        }
        __syncthreads();
        prefix = (prefix << 8) | s_bin;
    }
    const unsigned thr = prefix;           // exact key of k-th largest
    const unsigned r   = s_kneed;          // # of ==thr elements to keep

    unsigned ceq = 0, cgt = 0;
    #pragma unroll
    for (int e = 0; e < EPB; ++e) {
        if (key[e] > thr) cgt++;
        else if (key[e] == thr) ceq++;
    }
    unsigned eq_base = block_prefix_excl(ceq, s_wsum);
    unsigned eq_keep = (eq_base < r) ? min(r - eq_base, ceq) : 0u;
    unsigned slot    = block_prefix_excl(cgt + eq_keep, s_wsum);

    unsigned eqo = eq_base;
    #pragma unroll
    for (int e = 0; e < EPB; ++e) {
        bool keep = false;
        if (key[e] > thr) keep = true;
        else if (key[e] == thr) { keep = (eqo < r); eqo++; }
        if (keep) { out_idx[slot] = base + e; out_val[slot] = sdata[base + e]; slot++; }
    }
    __syncthreads();
}

// ---------------------------------------------------------------------------
// Bitonic sort of (val,idx) pairs, length L (power of 2 <= 256), 256 threads.
// Final order: descending value; ties -> ascending index (jax top_k order).
// ---------------------------------------------------------------------------
__device__ void sort_desc(float* v, int* idx, int L) {
    const int tid = threadIdx.x;
    for (int size = 2; size <= L; size <<= 1) {
        for (int stride = size >> 1; stride > 0; stride >>= 1) {
            __syncthreads();
            for (int i = tid; i < (L >> 1); i += 256) {
                int lo = 2 * i - (i & (stride - 1));
                int hi = lo + stride;
                float va = v[lo], vb = v[hi];
                int   ia = idx[lo], ib = idx[hi];
                bool aBeforeB = (va > vb) || (va == vb && ia < ib);
                bool dirDesc  = ((lo & size) == 0);
                if (dirDesc ? !aBeforeB : aBeforeB) {
                    v[lo] = vb; v[hi] = va;
                    idx[lo] = ib; idx[hi] = ia;
                }
            }
        }
    }
    __syncthreads();
}

// ---------------------------------------------------------------------------
// SGEMM: C[M,N] = gelu(A[M,K] * B[N,K]^T), row-major, fp32, sequential
// ascending-K accumulation via packed f32x2 FMA (each half = IEEE rn FMA,
// bitwise identical per element to the scalar version).
// 128x128 tile, BK=8, 256 threads, 8x(4x2) microtile, double-buffered smem.
// ---------------------------------------------------------------------------
template <int K>
__device__ __forceinline__ void sgemm_gelu_body(
    const float* __restrict__ A, const float* __restrict__ B,
    float* __restrict__ C, int N)
{
    constexpr int BK = 8, LDA = 132;
    __shared__ __align__(16) float sA[2][BK * LDA];
    __shared__ __align__(16) float sB[2][BK * LDA];
    const int tid = threadIdx.x;
    const int tx  = tid & 15, ty = tid >> 4;
    const int m0  = blockIdx.y * 128;
    const int n0  = blockIdx.x * 128;
    const int lrow = tid >> 1;
    const int lcol = (tid & 1) << 2;

    const float* Ag = A + (size_t)(m0 + lrow) * K + lcol;
    const float* Bg = B + (size_t)(n0 + lrow) * K + lcol;

    unsigned long long acc2[8][4];   // [m][n-pair]: halves = cols (2j, 2j+1)
    #pragma unroll
    for (int i = 0; i < 8; ++i)
        #pragma unroll
        for (int j = 0; j < 4; ++j) acc2[i][j] = 0ull;

    {   // preload tile 0
        float4 a = *(const float4*)Ag;
        float4 b = *(const float4*)Bg;
        sA[0][(lcol+0)*LDA+lrow]=a.x; sA[0][(lcol+1)*LDA+lrow]=a.y;
        sA[0][(lcol+2)*LDA+lrow]=a.z; sA[0][(lcol+3)*LDA+lrow]=a.w;
        sB[0][(lcol+0)*LDA+lrow]=b.x; sB[0][(lcol+1)*LDA+lrow]=b.y;
        sB[0][(lcol+2)*LDA+lrow]=b.z; sB[0][(lcol+3)*LDA+lrow]=b.w;
    }
    __syncthreads();

    constexpr int NT = K / BK;
    int cur = 0;
    for (int kt = 0; kt < NT; ++kt) {
        float4 an, bn;
        if (kt + 1 < NT) {
            an = *(const float4*)(Ag + (kt + 1) * BK);
            bn = *(const float4*)(Bg + (kt + 1) * BK);
        }
        #pragma unroll
        for (int kk = 0; kk < BK; ++kk) {
            float4 a0 = *(const float4*)&sA[cur][kk*LDA + ty*8];
            float4 a1 = *(const float4*)&sA[cur][kk*LDA + ty*8 + 4];
            // b columns as packed pairs: (2j, 2j+1) little-endian in each u64
            ulonglong2 b01 = *(const ulonglong2*)&sB[cur][kk*LDA + tx*8];
            ulonglong2 b23 = *(const ulonglong2*)&sB[cur][kk*LDA + tx*8 + 4];
            unsigned long long bb[4] = {b01.x, b01.y, b23.x, b23.y};
            float ar[8] = {a0.x,a0.y,a0.z,a0.w,a1.x,a1.y,a1.z,a1.w};
            #pragma unroll
            for (int i = 0; i < 8; ++i) {
                unsigned long long ad = dup2(ar[i]);
                #pragma unroll
                for (int j = 0; j < 4; ++j)
                    ffma2(acc2[i][j], ad, bb[j]);
            }
        }
        if (kt + 1 < NT) {
            int nxt = cur ^ 1;
            sA[nxt][(lcol+0)*LDA+lrow]=an.x; sA[nxt][(lcol+1)*LDA+lrow]=an.y;
            sA[nxt][(lcol+2)*LDA+lrow]=an.z; sA[nxt][(lcol+3)*LDA+lrow]=an.w;
            sB[nxt][(lcol+0)*LDA+lrow]=bn.x; sB[nxt][(lcol+1)*LDA+lrow]=bn.y;
            sB[nxt][(lcol+2)*LDA+lrow]=bn.z; sB[nxt][(lcol+3)*LDA+lrow]=bn.w;
            cur = nxt;
        }
        __syncthreads();
    }

    #pragma unroll
    for (int i = 0; i < 8; ++i) {
        float* Cr = C + (size_t)(m0 + ty*8 + i) * N + n0 + tx*8;
        float2 p0 = unpack2(acc2[i][0]);
        float2 p1 = unpack2(acc2[i][1]);
        float2 p2 = unpack2(acc2[i][2]);
        float2 p3 = unpack2(acc2[i][3]);
        float4 o0, o1;
        o0.x = gelu_f(p0.x); o0.y = gelu_f(p0.y);
        o0.z = gelu_f(p1.x); o0.w = gelu_f(p1.y);
        o1.x = gelu_f(p2.x); o1.y = gelu_f(p2.y);
        o1.z = gelu_f(p3.x); o1.w = gelu_f(p3.y);
        *(float4*)Cr       = o0;
        *(float4*)(Cr + 4) = o1;
    }
}

__global__ __launch_bounds__(256) void k_gemm1(const float* __restrict__ x,
                                               const float* __restrict__ ip) {
    sgemm_gelu_body<DMODEL>(x, ip, g_acts1, NIN);
}
__global__ __launch_bounds__(256) void k_gemm3(const float* __restrict__ oiw) {
    sgemm_gelu_body<DPV>(g_agg, oiw, g_acts3, NOUT);
}

// Transpose process_input_weights [NPROC, NIN] -> g_Wt [NIN, NPROC]
__global__ void k_transpose(const float* __restrict__ W) {
    __shared__ float tile[32][33];
    int x  = blockIdx.x * 32 + threadIdx.x;   // n_in index
    int y0 = blockIdx.y * 32;                 // proc index base
    #pragma unroll
    for (int j = 0; j < 32; j += 8)
        tile[threadIdx.y + j][threadIdx.x] = W[(size_t)(y0 + threadIdx.y + j) * NIN + x];
    __syncthreads();
    int px  = y0 + threadIdx.x;               // proc
    int iy0 = blockIdx.x * 32;                // n_in
    #pragma unroll
    for (int j = 0; j < 32; j += 8)
        g_Wt[(size_t)(iy0 + threadIdx.y + j) * NPROC + px] = tile[threadIdx.x][threadIdx.y + j];
}

// ---------------------------------------------------------------------------
// Stage 1+2 fused: load acts1 row -> top-256 (ascending-index slots) ->
// sparse gather-GEMM (ascending-n sequential FMA, reference order) -> gelu ->
// top-128 -> sort desc -> softmax (sequential, jax order) -> weighted value
// gather in sorted order -> g_agg.
// ---------------------------------------------------------------------------
__global__ __launch_bounds__(256) void k_stage2(const float* __restrict__ PV) {
    __shared__ float sdata[NIN];        // acts1 row (2048), then proc acts (1024)
    __shared__ int   sIdx[KIN];
    __shared__ float sVal[KIN];
    __shared__ int   pidx[KPROC];
    __shared__ float pval[KPROC];
    __shared__ float sexp[KPROC];
    __shared__ float sdenom;
    const int t   = blockIdx.x;
    const int tid = threadIdx.x;

    {   // load acts1 row (vectorized, 8 floats per thread)
        const float4* row = (const float4*)(g_acts1 + (size_t)t * NIN);
        float4 r0 = row[tid];
        float4 r1 = row[tid + 256];
        ((float4*)sdata)[tid]       = r0;
        ((float4*)sdata)[tid + 256] = r1;
    }
    __syncthreads();

    topk_fast<NIN / 256>(sdata, KIN, sIdx, sVal);   // stage-1 selection

    float a0 = 0.f, a1 = 0.f, a2 = 0.f, a3 = 0.f;
    #pragma unroll 8
    for (int j = 0; j < KIN; ++j) {         // ascending n (reference order)
        const float v = sVal[j];
        const float* w = g_Wt + (size_t)sIdx[j] * NPROC + tid;
        a0 = fmaf(v, w[0],   a0);
        a1 = fmaf(v, w[256], a1);
        a2 = fmaf(v, w[512], a2);
        a3 = fmaf(v, w[768], a3);
    }
    __syncthreads();
    sdata[tid]       = gelu_f(a0);
    sdata[tid + 256] = gelu_f(a1);
    sdata[tid + 512] = gelu_f(a2);
    sdata[tid + 768] = gelu_f(a3);
    __syncthreads();

    topk_fast<NPROC / 256>(sdata, KPROC, pidx, pval);
    sort_desc(pval, pidx, KPROC);           // jax top_k output order

    // softmax, jax order: max = pval[0]; sum sequentially over sorted k
    if (tid < KPROC) sexp[tid] = expf(pval[tid] - pval[0]);
    __syncthreads();
    if (tid == 0) {
        float s = 0.f;
        for (int j = 0; j < KPROC; ++j) s += sexp[j];
        sdenom = s;
    }
    __syncthreads();
    const float denom = sdenom;
    if (tid < KPROC) pval[tid] = __fdiv_rn(sexp[tid], denom);
    __syncthreads();

    // weighted value gather, sequential over sorted k (reference einsum order)
    float acc = 0.f;
    #pragma unroll 8
    for (int j = 0; j < KPROC; ++j)
        acc = fmaf(pval[j], PV[(size_t)pidx[j] * DPV + tid], acc);
    g_agg[(size_t)t * DPV + tid] = acc;
}

// Stage 3 fused: top-256 of 2048, sort desc, weighted pattern combine in
// sorted order (reference einsum order) -> out
__global__ __launch_bounds__(256) void k_stage3(const float* __restrict__ OP,
                                                float* __restrict__ out) {
    __shared__ float sdata[NOUT];
    __shared__ int   sidx[KOUT];
    __shared__ float sval[KOUT];
    const int t   = blockIdx.x;
    const int tid = threadIdx.x;
    {
        const float4* row = (const float4*)(g_acts3 + (size_t)t * NOUT);
        float4 r0 = row[tid];
        float4 r1 = row[tid + 256];
        ((float4*)sdata)[tid]       = r0;
        ((float4*)sdata)[tid + 256] = r1;
    }
    __syncthreads();
    topk_fast<NOUT / 256>(sdata, KOUT, sidx, sval);
    sort_desc(sval, sidx, KOUT);            // jax top_k output order

    float a0 = 0.f, a1 = 0.f;
    #pragma unroll 8
    for (int j = 0; j < KOUT; ++j) {        // sequential over sorted k
        const float v = sval[j];
        const float* p = OP + (size_t)sidx[j] * DMODEL + tid;
        a0 = fmaf(v, p[0],   a0);
        a1 = fmaf(v, p[256], a1);
    }
    out[(size_t)t * DMODEL + tid]       = a0;
    out[(size_t)t * DMODEL + tid + 256] = a1;
}

extern "C" void kernel_launch(void* const* d_in, const int* in_sizes, int n_in,
                              void* d_out, int out_size) {
    const float* x   = (const float*)d_in[0];  // [2,1024,512]
    const float* ip  = (const float*)d_in[1];  // [2048,512]
    const float* piw = (const float*)d_in[2];  // [1024,2048]
    const float* pv  = (const float*)d_in[3];  // [1024,256]
    const float* oiw = (const float*)d_in[4];  // [2048,256]
    const float* op  = (const float*)d_in[5];  // [2048,512]
    float* out = (float*)d_out;                // [2,1024,512]

    k_transpose<<<dim3(NIN / 32, NPROC / 32), dim3(32, 8)>>>(piw);
    k_gemm1<<<dim3(NIN / 128, TOK / 128), 256>>>(x, ip);
    k_stage2<<<TOK, 256>>>(pv);
    k_gemm3<<<dim3(NOUT / 128, TOK / 128), 256>>>(oiw);
    k_stage3<<<TOK, 256>>>(op, out);
}

// round 7
// speedup vs baseline: 1.1222x; 1.0321x over previous
#include <cuda_runtime.h>
#include <cstdint>

// Problem dims (fixed by the dataset)
#define TOK    2048   // B*S
#define DMODEL 512
#define NIN    2048
#define NPROC  1024
#define DPV    256
#define NOUT   2048
#define KIN    256
#define KPROC  128
#define KOUT   256

// Scratch (device globals — no dynamic allocation allowed)
__device__ float g_acts1[TOK * NIN];      // gelu(x @ IP^T)       16 MB
__device__ float g_Wt[NIN * NPROC];       // PIW^T (row-gather)    8 MB
__device__ float g_xT[DMODEL * TOK];      // x^T   (k-major A)     4 MB
__device__ float g_ipT[DMODEL * NIN];     // IP^T  (k-major B)     4 MB
__device__ float g_oiwT[DPV * NOUT];      // OIW^T (k-major B)     2 MB
__device__ float g_aggT[DPV * TOK];       // agg^T (k-major A)     2 MB
__device__ float g_acts3[TOK * NOUT];     // gelu(agg @ OIW^T)    16 MB

// ---------------------------------------------------------------------------
// XLA's f32 erf (what jax.lax.erf runs): clamp to [-4,4], x*P(x^2)/Q(x^2).
// ---------------------------------------------------------------------------
__device__ __forceinline__ float erf_xla(float x) {
    x = fminf(fmaxf(x, -4.0f), 4.0f);
    float x2 = x * x;
    float p = fmaf(x2, 0.00022905065861350646f, 0.0034082910107109506f);
    p = fmaf(x2, p, 0.050955695062380861f);
    p = fmaf(x2, p, 0.18520832239976145f);
    p = fmaf(x2, p, 1.128379143519084f);
    p = x * p;
    float q = fmaf(x2, -1.1791602954361697e-7f, 2.3547966471313185e-05f);
    q = fmaf(x2, q, 0.0010179625278914885f);
    q = fmaf(x2, q, 0.014070470171167667f);
    q = fmaf(x2, q, 0.11098505178285362f);
    q = fmaf(x2, q, 0.49746925110067538f);
    q = fmaf(x2, q, 1.0f);
    return __fdiv_rn(p, q);
}

// jax.nn.gelu(approximate=False): (x * (erf(x / sqrt2) + 1)) / 2
__device__ __forceinline__ float gelu_f(float x) {
    float t = __fdiv_rn(x, 1.41421356237309504880f);
    float e = erf_xla(t);
    return x * (e + 1.0f) * 0.5f;
}

// order-preserving float -> uint key (larger float => larger key)
__device__ __forceinline__ unsigned fkey(float f) {
    unsigned b = __float_as_uint(f);
    return b ^ ((b & 0x80000000u) ? 0xFFFFFFFFu : 0x80000000u);
}

// ---------------------------------------------------------------------------
// Packed f32x2 helpers (sm_103a). Each half = independent IEEE rn FMA,
// bitwise identical to scalar fmaf on that half.
// ---------------------------------------------------------------------------
__device__ __forceinline__ void ffma2(unsigned long long& d,
                                      unsigned long long a,
                                      unsigned long long b) {
    asm("fma.rn.f32x2 %0, %1, %2, %0;" : "+l"(d) : "l"(a), "l"(b));
}
__device__ __forceinline__ unsigned long long dup2(float x) {
    unsigned long long r;
    asm("mov.b64 %0, {%1, %1};" : "=l"(r) : "f"(x));
    return r;
}
__device__ __forceinline__ float2 unpack2(unsigned long long v) {
    float2 f;
    asm("mov.b64 {%0, %1}, %2;" : "=f"(f.x), "=f"(f.y) : "l"(v));
    return f;
}

// cp.async helpers
__device__ __forceinline__ void cp16(uint32_t smem, const void* g) {
    asm volatile("cp.async.ca.shared.global [%0], [%1], 16;"
                 :: "r"(smem), "l"(g));
}
__device__ __forceinline__ void cp_commit() {
    asm volatile("cp.async.commit_group;");
}
__device__ __forceinline__ void cp_wait1() {
    asm volatile("cp.async.wait_group 1;");
}

// ---------------------------------------------------------------------------
// Warp-shuffle scan primitives
// ---------------------------------------------------------------------------
__device__ __forceinline__ unsigned warp_suffix_incl(unsigned v, int lane) {
    #pragma unroll
    for (int off = 1; off < 32; off <<= 1) {
        unsigned o = __shfl_down_sync(0xffffffffu, v, off);
        if (lane + off < 32) v += o;
    }
    return v;
}
__device__ __forceinline__ unsigned warp_prefix_incl(unsigned v, int lane) {
    #pragma unroll
    for (int off = 1; off < 32; off <<= 1) {
        unsigned o = __shfl_up_sync(0xffffffffu, v, off);
        if (lane >= off) v += o;
    }
    return v;
}

// block-wide (256 thr) exclusive prefix sum; s_wsum is 8-entry scratch
__device__ __forceinline__ unsigned block_prefix_excl(unsigned x, unsigned* s_wsum) {
    const int tid = threadIdx.x, lane = tid & 31, wid = tid >> 5;
    unsigned v = warp_prefix_incl(x, lane);
    __syncthreads();
    if (lane == 31) s_wsum[wid] = v;
    __syncthreads();
    unsigned add = 0;
    #pragma unroll
    for (int w = 0; w < 8; ++w) if (w < wid) add += s_wsum[w];
    return v + add - x;
}

// ---------------------------------------------------------------------------
// Exact top-k for one row in shared memory. Block = 256 threads.
// jax.lax.top_k set semantics (lowest index wins ties); slots in
// ascending-index order. n = EPB*256.
// ---------------------------------------------------------------------------
template <int EPB>
__device__ void topk_fast(const float* sdata, int k, int* out_idx, float* out_val)
{
    __shared__ unsigned s_cnt[256];
    __shared__ unsigned s_wsum[8];
    __shared__ unsigned s_bin;
    __shared__ unsigned s_kneed;
    const int tid  = threadIdx.x, lane = tid & 31, wid = tid >> 5;
    const int base = tid * EPB;

    unsigned key[EPB];
    #pragma unroll
    for (int e = 0; e < EPB; ++e) key[e] = fkey(sdata[base + e]);

    if (tid == 0) s_kneed = (unsigned)k;
    unsigned prefix = 0;

    #pragma unroll
    for (int pass = 0; pass < 4; ++pass) {
        const int shift = 24 - 8 * pass;
        s_cnt[tid] = 0;
        __syncthreads();
        #pragma unroll
        for (int e = 0; e < EPB; ++e) {
            bool m;
            if (pass == 0) m = true;
            else           m = ((key[e] >> (shift + 8)) == prefix);
            if (m) atomicAdd(&s_cnt[(key[e] >> shift) & 255u], 1u);
        }
        __syncthreads();
        unsigned own = s_cnt[tid];
        unsigned v   = warp_suffix_incl(own, lane);   // lane0 = warp total
        if (lane == 0) s_wsum[wid] = v;
        __syncthreads();
        unsigned add = 0;
        #pragma unroll
        for (int w = 0; w < 8; ++w) if (w > wid) add += s_wsum[w];
        v += add;                                     // inclusive suffix over 256 bins
        unsigned kneed = s_kneed;
        __syncthreads();
        if (v >= kneed && (v - own) < kneed) {
            s_bin   = (unsigned)tid;
            s_kneed = kneed - (v - own);
        }
        __syncthreads();
        prefix = (prefix << 8) | s_bin;
    }
    const unsigned thr = prefix;
    const unsigned r   = s_kneed;

    unsigned ceq = 0, cgt = 0;
    #pragma unroll
    for (int e = 0; e < EPB; ++e) {
        if (key[e] > thr) cgt++;
        else if (key[e] == thr) ceq++;
    }
    unsigned eq_base = block_prefix_excl(ceq, s_wsum);
    unsigned eq_keep = (eq_base < r) ? min(r - eq_base, ceq) : 0u;
    unsigned slot    = block_prefix_excl(cgt + eq_keep, s_wsum);

    unsigned eqo = eq_base;
    #pragma unroll
    for (int e = 0; e < EPB; ++e) {
        bool keep = false;
        if (key[e] > thr) keep = true;
        else if (key[e] == thr) { keep = (eqo < r); eqo++; }
        if (keep) { out_idx[slot] = base + e; out_val[slot] = sdata[base + e]; slot++; }
    }
    __syncthreads();
}

// ---------------------------------------------------------------------------
// Bitonic sort of (val,idx) pairs, length L (power of 2 <= 256), 256 threads.
// Final order: descending value; ties -> ascending index (jax top_k order).
// ---------------------------------------------------------------------------
__device__ void sort_desc(float* v, int* idx, int L) {
    const int tid = threadIdx.x;
    for (int size = 2; size <= L; size <<= 1) {
        for (int stride = size >> 1; stride > 0; stride >>= 1) {
            __syncthreads();
            for (int i = tid; i < (L >> 1); i += 256) {
                int lo = 2 * i - (i & (stride - 1));
                int hi = lo + stride;
                float va = v[lo], vb = v[hi];
                int   ia = idx[lo], ib = idx[hi];
                bool aBeforeB = (va > vb) || (va == vb && ia < ib);
                bool dirDesc  = ((lo & size) == 0);
                if (dirDesc ? !aBeforeB : aBeforeB) {
                    v[lo] = vb; v[hi] = va;
                    idx[lo] = ib; idx[hi] = ia;
                }
            }
        }
    }
    __syncthreads();
}

// ---------------------------------------------------------------------------
// Generic 32x32-tile transpose: dst[c][r] = src[r][c]. R, C multiples of 32.
// ---------------------------------------------------------------------------
__global__ void k_transp(const float* __restrict__ src, float* __restrict__ dst,
                         int R, int C) {
    __shared__ float tile[32][33];
    int c0 = blockIdx.x * 32, r0 = blockIdx.y * 32;
    int tx = threadIdx.x, ty = threadIdx.y;
    #pragma unroll
    for (int j = 0; j < 32; j += 8)
        tile[ty + j][tx] = src[(size_t)(r0 + ty + j) * C + c0 + tx];
    __syncthreads();
    #pragma unroll
    for (int j = 0; j < 32; j += 8)
        dst[(size_t)(c0 + ty + j) * R + r0 + tx] = tile[tx][ty + j];
}

// ---------------------------------------------------------------------------
// GEMM with k-major operands: C[M][N] = gelu(sum_k At[k][m] * Bt[k][n]).
// cp.async 3-stage pipeline (global->smem, no register staging), 128x128
// tile, BK=8, 256 threads, 8x(4x2) f32x2 microtile. Accumulation: ascending
// k, sequential FFMA2 per element — bitwise identical to prior rounds.
// ---------------------------------------------------------------------------
template <int K>
__global__ __launch_bounds__(256) void k_gemm(
    const float* __restrict__ At,   // [K][Mtot]
    const float* __restrict__ Bt,   // [K][Ntot]
    float* __restrict__ C,          // [Mtot][Ntot]
    int Mtot, int Ntot)
{
    constexpr int BK = 8, STAGES = 3, NT = K / BK;
    __shared__ __align__(16) float sA[STAGES][BK * 128];
    __shared__ __align__(16) float sB[STAGES][BK * 128];
    const int tid = threadIdx.x;
    const int tx  = tid & 15, ty = tid >> 4;
    const int m0  = blockIdx.y * 128;
    const int n0  = blockIdx.x * 128;

    // cp.async element: tile is BK rows(k) x 128 cols, 1024 floats; each of
    // 256 threads copies one 16B chunk. r = k-row, c = col.
    const int cr = tid >> 5;            // 0..7
    const int cc = (tid & 31) << 2;     // 0,4,...,124
    const uint32_t sA0 = (uint32_t)__cvta_generic_to_shared(&sA[0][0]);
    const uint32_t sB0 = (uint32_t)__cvta_generic_to_shared(&sB[0][0]);
    const uint32_t soff = (uint32_t)((cr * 128 + cc) * 4);
    const float* gA = At + (size_t)cr * Mtot + m0 + cc;
    const float* gB = Bt + (size_t)cr * Ntot + n0 + cc;

    unsigned long long acc2[8][4];
    #pragma unroll
    for (int i = 0; i < 8; ++i)
        #pragma unroll
        for (int j = 0; j < 4; ++j) acc2[i][j] = 0ull;

    // prologue: prefetch stages 0,1
    #pragma unroll
    for (int s = 0; s < STAGES - 1; ++s) {
        cp16(sA0 + s * (BK * 128 * 4) + soff, gA + (size_t)s * BK * Mtot);
        cp16(sB0 + s * (BK * 128 * 4) + soff, gB + (size_t)s * BK * Ntot);
        cp_commit();
    }

    int stage = 0;
    for (int kt = 0; kt < NT; ++kt) {
        cp_wait1();            // oldest in-flight group (stage kt) complete
        __syncthreads();       // also: all warps done reading stage kt-1

        // prefetch stage kt+2 into the buffer freed by kt-1
        if (kt + STAGES - 1 < NT) {
            int ps = (stage + STAGES - 1) % STAGES;
            cp16(sA0 + ps * (BK * 128 * 4) + soff,
                 gA + (size_t)(kt + STAGES - 1) * BK * Mtot);
            cp16(sB0 + ps * (BK * 128 * 4) + soff,
                 gB + (size_t)(kt + STAGES - 1) * BK * Ntot);
        }
        cp_commit();           // always commit (possibly empty group)

        const float* a_s = &sA[stage][0];
        const float* b_s = &sB[stage][0];
        #pragma unroll
        for (int kk = 0; kk < BK; ++kk) {
            float4 a0 = *(const float4*)&a_s[kk * 128 + ty * 8];
            float4 a1 = *(const float4*)&a_s[kk * 128 + ty * 8 + 4];
            ulonglong2 b01 = *(const ulonglong2*)&b_s[kk * 128 + tx * 8];
            ulonglong2 b23 = *(const ulonglong2*)&b_s[kk * 128 + tx * 8 + 4];
            unsigned long long bb[4] = {b01.x, b01.y, b23.x, b23.y};
            float ar[8] = {a0.x, a0.y, a0.z, a0.w, a1.x, a1.y, a1.z, a1.w};
            #pragma unroll
            for (int i = 0; i < 8; ++i) {
                unsigned long long ad = dup2(ar[i]);
                #pragma unroll
                for (int j = 0; j < 4; ++j)
                    ffma2(acc2[i][j], ad, bb[j]);
            }
        }
        stage = (stage + 1) % STAGES;
    }

    #pragma unroll
    for (int i = 0; i < 8; ++i) {
        float* Cr = C + (size_t)(m0 + ty * 8 + i) * Ntot + n0 + tx * 8;
        float2 p0 = unpack2(acc2[i][0]);
        float2 p1 = unpack2(acc2[i][1]);
        float2 p2 = unpack2(acc2[i][2]);
        float2 p3 = unpack2(acc2[i][3]);
        float4 o0, o1;
        o0.x = gelu_f(p0.x); o0.y = gelu_f(p0.y);
        o0.z = gelu_f(p1.x); o0.w = gelu_f(p1.y);
        o1.x = gelu_f(p2.x); o1.y = gelu_f(p2.y);
        o1.z = gelu_f(p3.x); o1.w = gelu_f(p3.y);
        *(float4*)Cr       = o0;
        *(float4*)(Cr + 4) = o1;
    }
}

// ---------------------------------------------------------------------------
// Stage 1+2 fused: acts1 row -> top-256 -> sparse gather-GEMM (ascending-n
// sequential FMA, reference order) -> gelu -> top-128 -> sort desc ->
// softmax (sequential, jax order) -> weighted value gather -> g_aggT.
// ---------------------------------------------------------------------------
__global__ __launch_bounds__(256) void k_stage2(const float* __restrict__ PV) {
    __shared__ float sdata[NIN];
    __shared__ int   sIdx[KIN];
    __shared__ float sVal[KIN];
    __shared__ int   pidx[KPROC];
    __shared__ float pval[KPROC];
    __shared__ float sexp[KPROC];
    __shared__ float sdenom;
    const int t   = blockIdx.x;
    const int tid = threadIdx.x;

    {
        const float4* row = (const float4*)(g_acts1 + (size_t)t * NIN);
        float4 r0 = row[tid];
        float4 r1 = row[tid + 256];
        ((float4*)sdata)[tid]       = r0;
        ((float4*)sdata)[tid + 256] = r1;
    }
    __syncthreads();

    topk_fast<NIN / 256>(sdata, KIN, sIdx, sVal);

    float a0 = 0.f, a1 = 0.f, a2 = 0.f, a3 = 0.f;
    #pragma unroll 16
    for (int j = 0; j < KIN; ++j) {         // ascending n (reference order)
        const float v = sVal[j];
        const float* w = g_Wt + (size_t)sIdx[j] * NPROC + tid;
        a0 = fmaf(v, w[0],   a0);
        a1 = fmaf(v, w[256], a1);
        a2 = fmaf(v, w[512], a2);
        a3 = fmaf(v, w[768], a3);
    }
    __syncthreads();
    sdata[tid]       = gelu_f(a0);
    sdata[tid + 256] = gelu_f(a1);
    sdata[tid + 512] = gelu_f(a2);
    sdata[tid + 768] = gelu_f(a3);
    __syncthreads();

    topk_fast<NPROC / 256>(sdata, KPROC, pidx, pval);
    sort_desc(pval, pidx, KPROC);           // jax top_k output order

    if (tid < KPROC) sexp[tid] = expf(pval[tid] - pval[0]);
    __syncthreads();
    if (tid == 0) {
        float s = 0.f;
        for (int j = 0; j < KPROC; ++j) s += sexp[j];
        sdenom = s;
    }
    __syncthreads();
    const float denom = sdenom;
    if (tid < KPROC) pval[tid] = __fdiv_rn(sexp[tid], denom);
    __syncthreads();

    float acc = 0.f;
    #pragma unroll 16
    for (int j = 0; j < KPROC; ++j)
        acc = fmaf(pval[j], PV[(size_t)pidx[j] * DPV + tid], acc);
    g_aggT[(size_t)tid * TOK + t] = acc;    // write transposed (k-major for gemm3)
}

// Stage 3 fused: top-256 of 2048, sort desc, weighted pattern combine in
// sorted order (reference einsum order) -> out
__global__ __launch_bounds__(256) void k_stage3(const float* __restrict__ OP,
                                                float* __restrict__ out) {
    __shared__ float sdata[NOUT];
    __shared__ int   sidx[KOUT];
    __shared__ float sval[KOUT];
    const int t   = blockIdx.x;
    const int tid = threadIdx.x;
    {
        const float4* row = (const float4*)(g_acts3 + (size_t)t * NOUT);
        float4 r0 = row[tid];
        float4 r1 = row[tid + 256];
        ((float4*)sdata)[tid]       = r0;
        ((float4*)sdata)[tid + 256] = r1;
    }
    __syncthreads();
    topk_fast<NOUT / 256>(sdata, KOUT, sidx, sval);
    sort_desc(sval, sidx, KOUT);            // jax top_k output order

    float a0 = 0.f, a1 = 0.f;
    #pragma unroll 16
    for (int j = 0; j < KOUT; ++j) {        // sequential over sorted k
        const float v = sval[j];
        const float* p = OP + (size_t)sidx[j] * DMODEL + tid;
        a0 = fmaf(v, p[0],   a0);
        a1 = fmaf(v, p[256], a1);
    }
    out[(size_t)t * DMODEL + tid]       = a0;
    out[(size_t)t * DMODEL + tid + 256] = a1;
}

extern "C" void kernel_launch(void* const* d_in, const int* in_sizes, int n_in,
                              void* d_out, int out_size) {
    const float* x   = (const float*)d_in[0];  // [2,1024,512]
    const float* ip  = (const float*)d_in[1];  // [2048,512]
    const float* piw = (const float*)d_in[2];  // [1024,2048]
    const float* pv  = (const float*)d_in[3];  // [1024,256]
    const float* oiw = (const float*)d_in[4];  // [2048,256]
    const float* op  = (const float*)d_in[5];  // [2048,512]
    float* out = (float*)d_out;                // [2,1024,512]

    float* xT   = nullptr; cudaGetSymbolAddress((void**)&xT,   g_xT);
    float* ipT  = nullptr; cudaGetSymbolAddress((void**)&ipT,  g_ipT);
    float* oiwT = nullptr; cudaGetSymbolAddress((void**)&oiwT, g_oiwT);
    float* wt   = nullptr; cudaGetSymbolAddress((void**)&wt,   g_Wt);
    float* a1p  = nullptr; cudaGetSymbolAddress((void**)&a1p,  g_acts1);
    float* aggT = nullptr; cudaGetSymbolAddress((void**)&aggT, g_aggT);
    float* a3p  = nullptr; cudaGetSymbolAddress((void**)&a3p,  g_acts3);

    dim3 tb(32, 8);
    k_transp<<<dim3(DMODEL / 32, TOK / 32),   tb>>>(x,   xT,   TOK,   DMODEL);
    k_transp<<<dim3(DMODEL / 32, NIN / 32),   tb>>>(ip,  ipT,  NIN,   DMODEL);
    k_transp<<<dim3(DPV / 32,    NOUT / 32),  tb>>>(oiw, oiwT, NOUT,  DPV);
    k_transp<<<dim3(NIN / 32,    NPROC / 32), tb>>>(piw, wt,   NPROC, NIN);

    k_gemm<DMODEL><<<dim3(NIN / 128, TOK / 128), 256>>>(xT, ipT, a1p, TOK, NIN);
    k_stage2<<<TOK, 256>>>(pv);
    k_gemm<DPV><<<dim3(NOUT / 128, TOK / 128), 256>>>(aggT, oiwT, a3p, TOK, NOUT);
    k_stage3<<<TOK, 256>>>(op, out);
}

// round 8
// speedup vs baseline: 1.1422x; 1.0178x over previous
#include <cuda_runtime.h>
#include <cstdint>

// Problem dims (fixed by the dataset)
#define TOK    2048   // B*S
#define DMODEL 512
#define NIN    2048
#define NPROC  1024
#define DPV    256
#define NOUT   2048
#define KIN    256
#define KPROC  128
#define KOUT   256

// Scratch (device globals — no dynamic allocation allowed)
__device__ float g_acts1[TOK * NIN];      // gelu(x @ IP^T)       16 MB
__device__ float g_Wt[NIN * NPROC];       // PIW^T (row-gather)    8 MB
__device__ float g_xT[DMODEL * TOK];      // x^T   (k-major A)     4 MB
__device__ float g_ipT[DMODEL * NIN];     // IP^T  (k-major B)     4 MB
__device__ float g_oiwT[DPV * NOUT];      // OIW^T (k-major B)     2 MB
__device__ float g_aggT[DPV * TOK];       // agg^T (k-major A)     2 MB
__device__ float g_acts3[TOK * NOUT];     // gelu(agg @ OIW^T)    16 MB

// ---------------------------------------------------------------------------
// XLA's f32 erf (what jax.lax.erf runs): clamp to [-4,4], x*P(x^2)/Q(x^2).
// ---------------------------------------------------------------------------
__device__ __forceinline__ float erf_xla(float x) {
    x = fminf(fmaxf(x, -4.0f), 4.0f);
    float x2 = x * x;
    float p = fmaf(x2, 0.00022905065861350646f, 0.0034082910107109506f);
    p = fmaf(x2, p, 0.050955695062380861f);
    p = fmaf(x2, p, 0.18520832239976145f);
    p = fmaf(x2, p, 1.128379143519084f);
    p = x * p;
    float q = fmaf(x2, -1.1791602954361697e-7f, 2.3547966471313185e-05f);
    q = fmaf(x2, q, 0.0010179625278914885f);
    q = fmaf(x2, q, 0.014070470171167667f);
    q = fmaf(x2, q, 0.11098505178285362f);
    q = fmaf(x2, q, 0.49746925110067538f);
    q = fmaf(x2, q, 1.0f);
    return __fdiv_rn(p, q);
}

// jax.nn.gelu(approximate=False): (x * (erf(x / sqrt2) + 1)) / 2
__device__ __forceinline__ float gelu_f(float x) {
    float t = __fdiv_rn(x, 1.41421356237309504880f);
    float e = erf_xla(t);
    return x * (e + 1.0f) * 0.5f;
}

// order-preserving float -> uint key (larger float => larger key)
__device__ __forceinline__ unsigned fkey(float f) {
    unsigned b = __float_as_uint(f);
    return b ^ ((b & 0x80000000u) ? 0xFFFFFFFFu : 0x80000000u);
}

// ---------------------------------------------------------------------------
// Packed f32x2 helpers (sm_103a). Each half = independent IEEE rn FMA,
// bitwise identical to scalar fmaf on that half.
// ---------------------------------------------------------------------------
__device__ __forceinline__ void ffma2(unsigned long long& d,
                                      unsigned long long a,
                                      unsigned long long b) {
    asm("fma.rn.f32x2 %0, %1, %2, %0;" : "+l"(d) : "l"(a), "l"(b));
}
__device__ __forceinline__ unsigned long long dup2(float x) {
    unsigned long long r;
    asm("mov.b64 %0, {%1, %1};" : "=l"(r) : "f"(x));
    return r;
}
__device__ __forceinline__ float2 unpack2(unsigned long long v) {
    float2 f;
    asm("mov.b64 {%0, %1}, %2;" : "=f"(f.x), "=f"(f.y) : "l"(v));
    return f;
}

// cp.async helpers
__device__ __forceinline__ void cp16(uint32_t smem, const void* g) {
    asm volatile("cp.async.ca.shared.global [%0], [%1], 16;"
                 :: "r"(smem), "l"(g));
}
__device__ __forceinline__ void cp_commit() {
    asm volatile("cp.async.commit_group;");
}
__device__ __forceinline__ void cp_wait1() {
    asm volatile("cp.async.wait_group 1;");
}

// ---------------------------------------------------------------------------
// Warp-shuffle scan primitives
// ---------------------------------------------------------------------------
__device__ __forceinline__ unsigned warp_suffix_incl(unsigned v, int lane) {
    #pragma unroll
    for (int off = 1; off < 32; off <<= 1) {
        unsigned o = __shfl_down_sync(0xffffffffu, v, off);
        if (lane + off < 32) v += o;
    }
    return v;
}
__device__ __forceinline__ unsigned warp_prefix_incl(unsigned v, int lane) {
    #pragma unroll
    for (int off = 1; off < 32; off <<= 1) {
        unsigned o = __shfl_up_sync(0xffffffffu, v, off);
        if (lane >= off) v += o;
    }
    return v;
}

// block-wide (256 thr) exclusive prefix sum; s_wsum is 8-entry scratch
__device__ __forceinline__ unsigned block_prefix_excl(unsigned x, unsigned* s_wsum) {
    const int tid = threadIdx.x, lane = tid & 31, wid = tid >> 5;
    unsigned v = warp_prefix_incl(x, lane);
    __syncthreads();
    if (lane == 31) s_wsum[wid] = v;
    __syncthreads();
    unsigned add = 0;
    #pragma unroll
    for (int w = 0; w < 8; ++w) if (w < wid) add += s_wsum[w];
    return v + add - x;
}

// ---------------------------------------------------------------------------
// Exact top-k for one row in shared memory. Block = 256 threads.
// jax.lax.top_k set semantics (lowest index wins ties); slots in
// ascending-index order. n = EPB*256.
// ---------------------------------------------------------------------------
template <int EPB>
__device__ void topk_fast(const float* sdata, int k, int* out_idx, float* out_val)
{
    __shared__ unsigned s_cnt[256];
    __shared__ unsigned s_wsum[8];
    __shared__ unsigned s_bin;
    __shared__ unsigned s_kneed;
    const int tid  = threadIdx.x, lane = tid & 31, wid = tid >> 5;
    const int base = tid * EPB;

    unsigned key[EPB];
    #pragma unroll
    for (int e = 0; e < EPB; ++e) key[e] = fkey(sdata[base + e]);

    if (tid == 0) s_kneed = (unsigned)k;
    unsigned prefix = 0;

    #pragma unroll
    for (int pass = 0; pass < 4; ++pass) {
        const int shift = 24 - 8 * pass;
        s_cnt[tid] = 0;
        __syncthreads();
        #pragma unroll
        for (int e = 0; e < EPB; ++e) {
            bool m;
            if (pass == 0) m = true;
            else           m = ((key[e] >> (shift + 8)) == prefix);
            if (m) atomicAdd(&s_cnt[(key[e] >> shift) & 255u], 1u);
        }
        __syncthreads();
        unsigned own = s_cnt[tid];
        unsigned v   = warp_suffix_incl(own, lane);   // lane0 = warp total
        if (lane == 0) s_wsum[wid] = v;
        __syncthreads();
        unsigned add = 0;
        #pragma unroll
        for (int w = 0; w < 8; ++w) if (w > wid) add += s_wsum[w];
        v += add;                                     // inclusive suffix over 256 bins
        unsigned kneed = s_kneed;
        __syncthreads();
        if (v >= kneed && (v - own) < kneed) {
            s_bin   = (unsigned)tid;
            s_kneed = kneed - (v - own);
        }
        __syncthreads();
        prefix = (prefix << 8) | s_bin;
    }
    const unsigned thr = prefix;
    const unsigned r   = s_kneed;

    unsigned ceq = 0, cgt = 0;
    #pragma unroll
    for (int e = 0; e < EPB; ++e) {
        if (key[e] > thr) cgt++;
        else if (key[e] == thr) ceq++;
    }
    unsigned eq_base = block_prefix_excl(ceq, s_wsum);
    unsigned eq_keep = (eq_base < r) ? min(r - eq_base, ceq) : 0u;
    unsigned slot    = block_prefix_excl(cgt + eq_keep, s_wsum);

    unsigned eqo = eq_base;
    #pragma unroll
    for (int e = 0; e < EPB; ++e) {
        bool keep = false;
        if (key[e] > thr) keep = true;
        else if (key[e] == thr) { keep = (eqo < r); eqo++; }
        if (keep) { out_idx[slot] = base + e; out_val[slot] = sdata[base + e]; slot++; }
    }
    __syncthreads();
}

// ---------------------------------------------------------------------------
// Bitonic sort of (val,idx) pairs, length L (power of 2 <= 256), 256 threads.
// Final order: descending value; ties -> ascending index (jax top_k order).
// ---------------------------------------------------------------------------
__device__ void sort_desc(float* v, int* idx, int L) {
    const int tid = threadIdx.x;
    for (int size = 2; size <= L; size <<= 1) {
        for (int stride = size >> 1; stride > 0; stride >>= 1) {
            __syncthreads();
            for (int i = tid; i < (L >> 1); i += 256) {
                int lo = 2 * i - (i & (stride - 1));
                int hi = lo + stride;
                float va = v[lo], vb = v[hi];
                int   ia = idx[lo], ib = idx[hi];
                bool aBeforeB = (va > vb) || (va == vb && ia < ib);
                bool dirDesc  = ((lo & size) == 0);
                if (dirDesc ? !aBeforeB : aBeforeB) {
                    v[lo] = vb; v[hi] = va;
                    idx[lo] = ib; idx[hi] = ia;
                }
            }
        }
    }
    __syncthreads();
}

// ---------------------------------------------------------------------------
// All four input transposes fused in one launch. Linearized block index:
//   [0,1024)    x   [2048,512]  -> g_xT
//   [1024,2048) ip  [2048,512]  -> g_ipT
//   [2048,2560) oiw [2048,256]  -> g_oiwT
//   [2560,4608) piw [1024,2048] -> g_Wt
// ---------------------------------------------------------------------------
__global__ void k_transp_all(const float* __restrict__ x,
                             const float* __restrict__ ip,
                             const float* __restrict__ oiw,
                             const float* __restrict__ piw) {
    __shared__ float tile[32][33];
    int b = blockIdx.x;
    const float* src; float* dst; int R, C, bx, by;
    if (b < 1024)      { src = x;   dst = g_xT;   R = TOK;   C = DMODEL; bx = b & 15;  by = b >> 4; }
    else if (b < 2048) { b -= 1024; src = ip;  dst = g_ipT;  R = NIN;   C = DMODEL; bx = b & 15;  by = b >> 4; }
    else if (b < 2560) { b -= 2048; src = oiw; dst = g_oiwT; R = NOUT;  C = DPV;    bx = b & 7;   by = b >> 3; }
    else               { b -= 2560; src = piw; dst = g_Wt;   R = NPROC; C = NIN;    bx = b & 63;  by = b >> 6; }
    int c0 = bx * 32, r0 = by * 32;
    int tx = threadIdx.x, ty = threadIdx.y;
    #pragma unroll
    for (int j = 0; j < 32; j += 8)
        tile[ty + j][tx] = src[(size_t)(r0 + ty + j) * C + c0 + tx];
    __syncthreads();
    #pragma unroll
    for (int j = 0; j < 32; j += 8)
        dst[(size_t)(c0 + ty + j) * R + r0 + tx] = tile[tx][ty + j];
}

// ---------------------------------------------------------------------------
// GEMM with k-major operands: C[M][N] = gelu(sum_k At[k][m] * Bt[k][n]).
// cp.async 3-stage pipeline, 128x128 tile, BK=16, 256 threads, 8x(4x2)
// f32x2 microtile. Ascending-k sequential FFMA2 chain per element —
// bitwise identical to prior rounds.
// ---------------------------------------------------------------------------
template <int K>
__global__ __launch_bounds__(256, 2) void k_gemm(
    const float* __restrict__ At,   // [K][Mtot]
    const float* __restrict__ Bt,   // [K][Ntot]
    float* __restrict__ C,          // [Mtot][Ntot]
    int Mtot, int Ntot)
{
    constexpr int BK = 16, STAGES = 3, NT = K / BK;
    constexpr int TILE_FLOATS = BK * 128;          // 2048 floats / operand / stage
    __shared__ __align__(16) float sA[STAGES][TILE_FLOATS];
    __shared__ __align__(16) float sB[STAGES][TILE_FLOATS];
    const int tid = threadIdx.x;
    const int tx  = tid & 15, ty = tid >> 4;
    const int m0  = blockIdx.y * 128;
    const int n0  = blockIdx.x * 128;

    // cp.async mapping: each thread copies two 16B chunks per operand:
    // rows cr and cr+8 of the BK x 128 tile.
    const int cr = tid >> 5;            // 0..7
    const int cc = (tid & 31) << 2;     // 0,4,...,124
    const uint32_t sA0 = (uint32_t)__cvta_generic_to_shared(&sA[0][0]);
    const uint32_t sB0 = (uint32_t)__cvta_generic_to_shared(&sB[0][0]);
    const uint32_t so0 = (uint32_t)((cr * 128 + cc) * 4);
    const uint32_t so1 = (uint32_t)(((cr + 8) * 128 + cc) * 4);
    const float* gA0 = At + (size_t)cr * Mtot + m0 + cc;
    const float* gA1 = At + (size_t)(cr + 8) * Mtot + m0 + cc;
    const float* gB0 = Bt + (size_t)cr * Ntot + n0 + cc;
    const float* gB1 = Bt + (size_t)(cr + 8) * Ntot + n0 + cc;

    unsigned long long acc2[8][4];
    #pragma unroll
    for (int i = 0; i < 8; ++i)
        #pragma unroll
        for (int j = 0; j < 4; ++j) acc2[i][j] = 0ull;

    // prologue: prefetch stages 0,1
    #pragma unroll
    for (int s = 0; s < STAGES - 1; ++s) {
        const size_t gk = (size_t)s * BK;
        cp16(sA0 + s * (TILE_FLOATS * 4) + so0, gA0 + gk * Mtot);
        cp16(sA0 + s * (TILE_FLOATS * 4) + so1, gA1 + gk * Mtot);
        cp16(sB0 + s * (TILE_FLOATS * 4) + so0, gB0 + gk * Ntot);
        cp16(sB0 + s * (TILE_FLOATS * 4) + so1, gB1 + gk * Ntot);
        cp_commit();
    }

    int stage = 0;
    for (int kt = 0; kt < NT; ++kt) {
        cp_wait1();            // oldest in-flight group complete
        __syncthreads();

        if (kt + STAGES - 1 < NT) {
            int ps = (stage + STAGES - 1) % STAGES;
            const size_t gk = (size_t)(kt + STAGES - 1) * BK;
            cp16(sA0 + ps * (TILE_FLOATS * 4) + so0, gA0 + gk * Mtot);
            cp16(sA0 + ps * (TILE_FLOATS * 4) + so1, gA1 + gk * Mtot);
            cp16(sB0 + ps * (TILE_FLOATS * 4) + so0, gB0 + gk * Ntot);
            cp16(sB0 + ps * (TILE_FLOATS * 4) + so1, gB1 + gk * Ntot);
        }
        cp_commit();           // always commit (possibly empty group)

        const float* a_s = &sA[stage][0];
        const float* b_s = &sB[stage][0];
        #pragma unroll
        for (int kk = 0; kk < BK; ++kk) {
            float4 a0 = *(const float4*)&a_s[kk * 128 + ty * 8];
            float4 a1 = *(const float4*)&a_s[kk * 128 + ty * 8 + 4];
            ulonglong2 b01 = *(const ulonglong2*)&b_s[kk * 128 + tx * 8];
            ulonglong2 b23 = *(const ulonglong2*)&b_s[kk * 128 + tx * 8 + 4];
            unsigned long long bb[4] = {b01.x, b01.y, b23.x, b23.y};
            float ar[8] = {a0.x, a0.y, a0.z, a0.w, a1.x, a1.y, a1.z, a1.w};
            #pragma unroll
            for (int i = 0; i < 8; ++i) {
                unsigned long long ad = dup2(ar[i]);
                #pragma unroll
                for (int j = 0; j < 4; ++j)
                    ffma2(acc2[i][j], ad, bb[j]);
            }
        }
        stage = (stage + 1) % STAGES;
    }

    #pragma unroll
    for (int i = 0; i < 8; ++i) {
        float* Cr = C + (size_t)(m0 + ty * 8 + i) * Ntot + n0 + tx * 8;
        float2 p0 = unpack2(acc2[i][0]);
        float2 p1 = unpack2(acc2[i][1]);
        float2 p2 = unpack2(acc2[i][2]);
        float2 p3 = unpack2(acc2[i][3]);
        float4 o0, o1;
        o0.x = gelu_f(p0.x); o0.y = gelu_f(p0.y);
        o0.z = gelu_f(p1.x); o0.w = gelu_f(p1.y);
        o1.x = gelu_f(p2.x); o1.y = gelu_f(p2.y);
        o1.z = gelu_f(p3.x); o1.w = gelu_f(p3.y);
        *(float4*)Cr       = o0;
        *(float4*)(Cr + 4) = o1;
    }
}

// ---------------------------------------------------------------------------
// Stage 1+2 fused: acts1 row -> top-256 -> sparse gather-GEMM (ascending-n
// sequential FMA, reference order) -> gelu -> top-128 -> sort desc ->
// softmax (sequential, jax order) -> weighted value gather -> g_aggT.
// ---------------------------------------------------------------------------
__global__ __launch_bounds__(256) void k_stage2(const float* __restrict__ PV) {
    __shared__ float sdata[NIN];
    __shared__ int   sIdx[KIN];
    __shared__ float sVal[KIN];
    __shared__ int   pidx[KPROC];
    __shared__ float pval[KPROC];
    __shared__ float sexp[KPROC];
    __shared__ float sdenom;
    const int t   = blockIdx.x;
    const int tid = threadIdx.x;

    {
        const float4* row = (const float4*)(g_acts1 + (size_t)t * NIN);
        float4 r0 = row[tid];
        float4 r1 = row[tid + 256];
        ((float4*)sdata)[tid]       = r0;
        ((float4*)sdata)[tid + 256] = r1;
    }
    __syncthreads();

    topk_fast<NIN / 256>(sdata, KIN, sIdx, sVal);

    float a0 = 0.f, a1 = 0.f, a2 = 0.f, a3 = 0.f;
    #pragma unroll 16
    for (int j = 0; j < KIN; ++j) {         // ascending n (reference order)
        const float v = sVal[j];
        const float* w = g_Wt + (size_t)sIdx[j] * NPROC + tid;
        a0 = fmaf(v, w[0],   a0);
        a1 = fmaf(v, w[256], a1);
        a2 = fmaf(v, w[512], a2);
        a3 = fmaf(v, w[768], a3);
    }
    __syncthreads();
    sdata[tid]       = gelu_f(a0);
    sdata[tid + 256] = gelu_f(a1);
    sdata[tid + 512] = gelu_f(a2);
    sdata[tid + 768] = gelu_f(a3);
    __syncthreads();

    topk_fast<NPROC / 256>(sdata, KPROC, pidx, pval);
    sort_desc(pval, pidx, KPROC);           // jax top_k output order

    if (tid < KPROC) sexp[tid] = expf(pval[tid] - pval[0]);
    __syncthreads();
    if (tid == 0) {
        float s = 0.f;
        for (int j = 0; j < KPROC; ++j) s += sexp[j];
        sdenom = s;
    }
    __syncthreads();
    const float denom = sdenom;
    if (tid < KPROC) pval[tid] = __fdiv_rn(sexp[tid], denom);
    __syncthreads();

    float acc = 0.f;
    #pragma unroll 16
    for (int j = 0; j < KPROC; ++j)
        acc = fmaf(pval[j], PV[(size_t)pidx[j] * DPV + tid], acc);
    g_aggT[(size_t)tid * TOK + t] = acc;    // transposed (k-major for gemm3)
}

// Stage 3 fused: top-256 of 2048, sort desc, weighted pattern combine in
// sorted order (reference einsum order) -> out
__global__ __launch_bounds__(256) void k_stage3(const float* __restrict__ OP,
                                                float* __restrict__ out) {
    __shared__ float sdata[NOUT];
    __shared__ int   sidx[KOUT];
    __shared__ float sval[KOUT];
    const int t   = blockIdx.x;
    const int tid = threadIdx.x;
    {
        const float4* row = (const float4*)(g_acts3 + (size_t)t * NOUT);
        float4 r0 = row[tid];
        float4 r1 = row[tid + 256];
        ((float4*)sdata)[tid]       = r0;
        ((float4*)sdata)[tid + 256] = r1;
    }
    __syncthreads();
    topk_fast<NOUT / 256>(sdata, KOUT, sidx, sval);
    sort_desc(sval, sidx, KOUT);            // jax top_k output order

    float a0 = 0.f, a1 = 0.f;
    #pragma unroll 16
    for (int j = 0; j < KOUT; ++j) {        // sequential over sorted k
        const float v = sval[j];
        const float* p = OP + (size_t)sidx[j] * DMODEL + tid;
        a0 = fmaf(v, p[0],   a0);
        a1 = fmaf(v, p[256], a1);
    }
    out[(size_t)t * DMODEL + tid]       = a0;
    out[(size_t)t * DMODEL + tid + 256] = a1;
}

extern "C" void kernel_launch(void* const* d_in, const int* in_sizes, int n_in,
                              void* d_out, int out_size) {
    const float* x   = (const float*)d_in[0];  // [2,1024,512]
    const float* ip  = (const float*)d_in[1];  // [2048,512]
    const float* piw = (const float*)d_in[2];  // [1024,2048]
    const float* pv  = (const float*)d_in[3];  // [1024,256]
    const float* oiw = (const float*)d_in[4];  // [2048,256]
    const float* op  = (const float*)d_in[5];  // [2048,512]
    float* out = (float*)d_out;                // [2,1024,512]

    float* xT   = nullptr; cudaGetSymbolAddress((void**)&xT,   g_xT);
    float* ipT  = nullptr; cudaGetSymbolAddress((void**)&ipT,  g_ipT);
    float* oiwT = nullptr; cudaGetSymbolAddress((void**)&oiwT, g_oiwT);
    float* a1p  = nullptr; cudaGetSymbolAddress((void**)&a1p,  g_acts1);
    float* aggT = nullptr; cudaGetSymbolAddress((void**)&aggT, g_aggT);
    float* a3p  = nullptr; cudaGetSymbolAddress((void**)&a3p,  g_acts3);

    k_transp_all<<<4608, dim3(32, 8)>>>(x, ip, oiw, piw);
    k_gemm<DMODEL><<<dim3(NIN / 128, TOK / 128), 256>>>(xT, ipT, a1p, TOK, NIN);
    k_stage2<<<TOK, 256>>>(pv);
    k_gemm<DPV><<<dim3(NOUT / 128, TOK / 128), 256>>>(aggT, oiwT, a3p, TOK, NOUT);
    k_stage3<<<TOK, 256>>>(op, out);
}

// round 9
// speedup vs baseline: 1.1831x; 1.0358x over previous
#include <cuda_runtime.h>
#include <cstdint>

// Problem dims (fixed by the dataset)
#define TOK    2048   // B*S
#define DMODEL 512
#define NIN    2048
#define NPROC  1024
#define DPV    256
#define NOUT   2048
#define KIN    256
#define KPROC  128
#define KOUT   256

// Scratch (device globals — no dynamic allocation allowed)
__device__ float g_acts1[TOK * NIN];      // gelu(x @ IP^T)       16 MB
__device__ float g_Wt[NIN * NPROC];       // PIW^T (row-gather)    8 MB
__device__ float g_xT[DMODEL * TOK];      // x^T   (k-major A)     4 MB
__device__ float g_ipT[DMODEL * NIN];     // IP^T  (k-major B)     4 MB
__device__ float g_oiwT[DPV * NOUT];      // OIW^T (k-major B)     2 MB
__device__ float g_aggT[DPV * TOK];       // agg^T (k-major A)     2 MB
__device__ float g_acts3[TOK * NOUT];     // gelu(agg @ OIW^T)    16 MB

// ---------------------------------------------------------------------------
// XLA's f32 erf (what jax.lax.erf runs): clamp to [-4,4], x*P(x^2)/Q(x^2).
// ---------------------------------------------------------------------------
__device__ __forceinline__ float erf_xla(float x) {
    x = fminf(fmaxf(x, -4.0f), 4.0f);
    float x2 = x * x;
    float p = fmaf(x2, 0.00022905065861350646f, 0.0034082910107109506f);
    p = fmaf(x2, p, 0.050955695062380861f);
    p = fmaf(x2, p, 0.18520832239976145f);
    p = fmaf(x2, p, 1.128379143519084f);
    p = x * p;
    float q = fmaf(x2, -1.1791602954361697e-7f, 2.3547966471313185e-05f);
    q = fmaf(x2, q, 0.0010179625278914885f);
    q = fmaf(x2, q, 0.014070470171167667f);
    q = fmaf(x2, q, 0.11098505178285362f);
    q = fmaf(x2, q, 0.49746925110067538f);
    q = fmaf(x2, q, 1.0f);
    return __fdiv_rn(p, q);
}

// jax.nn.gelu(approximate=False): (x * (erf(x / sqrt2) + 1)) / 2
__device__ __forceinline__ float gelu_f(float x) {
    float t = __fdiv_rn(x, 1.41421356237309504880f);
    float e = erf_xla(t);
    return x * (e + 1.0f) * 0.5f;
}

// order-preserving float -> uint key (larger float => larger key)
__device__ __forceinline__ unsigned fkey(float f) {
    unsigned b = __float_as_uint(f);
    return b ^ ((b & 0x80000000u) ? 0xFFFFFFFFu : 0x80000000u);
}

// ---------------------------------------------------------------------------
// Packed f32x2 helpers (sm_103a). Each half = independent IEEE rn FMA,
// bitwise identical to scalar fmaf on that half.
// ---------------------------------------------------------------------------
__device__ __forceinline__ void ffma2(unsigned long long& d,
                                      unsigned long long a,
                                      unsigned long long b) {
    asm("fma.rn.f32x2 %0, %1, %2, %0;" : "+l"(d) : "l"(a), "l"(b));
}
__device__ __forceinline__ unsigned long long dup2(float x) {
    unsigned long long r;
    asm("mov.b64 %0, {%1, %1};" : "=l"(r) : "f"(x));
    return r;
}
__device__ __forceinline__ float2 unpack2(unsigned long long v) {
    float2 f;
    asm("mov.b64 {%0, %1}, %2;" : "=f"(f.x), "=f"(f.y) : "l"(v));
    return f;
}

// cp.async helpers
__device__ __forceinline__ void cp16(uint32_t smem, const void* g) {
    asm volatile("cp.async.ca.shared.global [%0], [%1], 16;"
                 :: "r"(smem), "l"(g));
}
__device__ __forceinline__ void cp_commit() {
    asm volatile("cp.async.commit_group;");
}
__device__ __forceinline__ void cp_wait1() {
    asm volatile("cp.async.wait_group 1;");
}

// ---------------------------------------------------------------------------
// Warp-shuffle scan primitives
// ---------------------------------------------------------------------------
__device__ __forceinline__ unsigned warp_suffix_incl(unsigned v, int lane) {
    #pragma unroll
    for (int off = 1; off < 32; off <<= 1) {
        unsigned o = __shfl_down_sync(0xffffffffu, v, off);
        if (lane + off < 32) v += o;
    }
    return v;
}
__device__ __forceinline__ unsigned warp_prefix_incl(unsigned v, int lane) {
    #pragma unroll
    for (int off = 1; off < 32; off <<= 1) {
        unsigned o = __shfl_up_sync(0xffffffffu, v, off);
        if (lane >= off) v += o;
    }
    return v;
}

// block-wide (256 thr) exclusive prefix sum; s_wsum is 8-entry scratch
__device__ __forceinline__ unsigned block_prefix_excl(unsigned x, unsigned* s_wsum) {
    const int tid = threadIdx.x, lane = tid & 31, wid = tid >> 5;
    unsigned v = warp_prefix_incl(x, lane);
    __syncthreads();
    if (lane == 31) s_wsum[wid] = v;
    __syncthreads();
    unsigned add = 0;
    #pragma unroll
    for (int w = 0; w < 8; ++w) if (w < wid) add += s_wsum[w];
    return v + add - x;
}

// ---------------------------------------------------------------------------
// Exact top-k for one row in shared memory. Block = 256 threads.
// jax.lax.top_k set semantics (lowest index wins ties); slots in
// ascending-index order. n = EPB*256.
// ---------------------------------------------------------------------------
template <int EPB>
__device__ void topk_fast(const float* sdata, int k, int* out_idx, float* out_val)
{
    __shared__ unsigned s_cnt[256];
    __shared__ unsigned s_wsum[8];
    __shared__ unsigned s_bin;
    __shared__ unsigned s_kneed;
    const int tid  = threadIdx.x, lane = tid & 31, wid = tid >> 5;
    const int base = tid * EPB;

    unsigned key[EPB];
    #pragma unroll
    for (int e = 0; e < EPB; ++e) key[e] = fkey(sdata[base + e]);

    if (tid == 0) s_kneed = (unsigned)k;
    unsigned prefix = 0;

    #pragma unroll
    for (int pass = 0; pass < 4; ++pass) {
        const int shift = 24 - 8 * pass;
        s_cnt[tid] = 0;
        __syncthreads();
        #pragma unroll
        for (int e = 0; e < EPB; ++e) {
            bool m;
            if (pass == 0) m = true;
            else           m = ((key[e] >> (shift + 8)) == prefix);
            if (m) atomicAdd(&s_cnt[(key[e] >> shift) & 255u], 1u);
        }
        __syncthreads();
        unsigned own = s_cnt[tid];
        unsigned v   = warp_suffix_incl(own, lane);   // lane0 = warp total
        if (lane == 0) s_wsum[wid] = v;
        __syncthreads();
        unsigned add = 0;
        #pragma unroll
        for (int w = 0; w < 8; ++w) if (w > wid) add += s_wsum[w];
        v += add;                                     // inclusive suffix over 256 bins
        unsigned kneed = s_kneed;
        __syncthreads();
        if (v >= kneed && (v - own) < kneed) {
            s_bin   = (unsigned)tid;
            s_kneed = kneed - (v - own);
        }
        __syncthreads();
        prefix = (prefix << 8) | s_bin;
    }
    const unsigned thr = prefix;
    const unsigned r   = s_kneed;

    unsigned ceq = 0, cgt = 0;
    #pragma unroll
    for (int e = 0; e < EPB; ++e) {
        if (key[e] > thr) cgt++;
        else if (key[e] == thr) ceq++;
    }
    unsigned eq_base = block_prefix_excl(ceq, s_wsum);
    unsigned eq_keep = (eq_base < r) ? min(r - eq_base, ceq) : 0u;
    unsigned slot    = block_prefix_excl(cgt + eq_keep, s_wsum);

    unsigned eqo = eq_base;
    #pragma unroll
    for (int e = 0; e < EPB; ++e) {
        bool keep = false;
        if (key[e] > thr) keep = true;
        else if (key[e] == thr) { keep = (eqo < r); eqo++; }
        if (keep) { out_idx[slot] = base + e; out_val[slot] = sdata[base + e]; slot++; }
    }
    __syncthreads();
}

// ---------------------------------------------------------------------------
// Bitonic sort of (val,idx) pairs, length L (power of 2 <= 256), 256 threads.
// Final order: descending value; ties -> ascending index (jax top_k order).
// ---------------------------------------------------------------------------
__device__ void sort_desc(float* v, int* idx, int L) {
    const int tid = threadIdx.x;
    for (int size = 2; size <= L; size <<= 1) {
        for (int stride = size >> 1; stride > 0; stride >>= 1) {
            __syncthreads();
            for (int i = tid; i < (L >> 1); i += 256) {
                int lo = 2 * i - (i & (stride - 1));
                int hi = lo + stride;
                float va = v[lo], vb = v[hi];
                int   ia = idx[lo], ib = idx[hi];
                bool aBeforeB = (va > vb) || (va == vb && ia < ib);
                bool dirDesc  = ((lo & size) == 0);
                if (dirDesc ? !aBeforeB : aBeforeB) {
                    v[lo] = vb; v[hi] = va;
                    idx[lo] = ib; idx[hi] = ia;
                }
            }
        }
    }
    __syncthreads();
}

// ---------------------------------------------------------------------------
// All four input transposes fused in one launch. Linearized block index:
//   [0,1024)    x   [2048,512]  -> g_xT
//   [1024,2048) ip  [2048,512]  -> g_ipT
//   [2048,2560) oiw [2048,256]  -> g_oiwT
//   [2560,4608) piw [1024,2048] -> g_Wt
// ---------------------------------------------------------------------------
__global__ void k_transp_all(const float* __restrict__ x,
                             const float* __restrict__ ip,
                             const float* __restrict__ oiw,
                             const float* __restrict__ piw) {
    __shared__ float tile[32][33];
    int b = blockIdx.x;
    const float* src; float* dst; int R, C, bx, by;
    if (b < 1024)      { src = x;   dst = g_xT;   R = TOK;   C = DMODEL; bx = b & 15;  by = b >> 4; }
    else if (b < 2048) { b -= 1024; src = ip;  dst = g_ipT;  R = NIN;   C = DMODEL; bx = b & 15;  by = b >> 4; }
    else if (b < 2560) { b -= 2048; src = oiw; dst = g_oiwT; R = NOUT;  C = DPV;    bx = b & 7;   by = b >> 3; }
    else               { b -= 2560; src = piw; dst = g_Wt;   R = NPROC; C = NIN;    bx = b & 63;  by = b >> 6; }
    int c0 = bx * 32, r0 = by * 32;
    int tx = threadIdx.x, ty = threadIdx.y;
    #pragma unroll
    for (int j = 0; j < 32; j += 8)
        tile[ty + j][tx] = src[(size_t)(r0 + ty + j) * C + c0 + tx];
    __syncthreads();
    #pragma unroll
    for (int j = 0; j < 32; j += 8)
        dst[(size_t)(c0 + ty + j) * R + r0 + tx] = tile[tx][ty + j];
}

// ---------------------------------------------------------------------------
// GEMM with k-major operands: C[M][N] = gelu(sum_k At[k][m] * Bt[k][n]).
// cp.async 3-stage pipeline, 128x128 tile, BK=32 (dynamic smem, 96KB/CTA),
// 256 threads, 8x(4x2) f32x2 microtile. Ascending-k sequential FFMA2 chain
// per element — bitwise identical to prior rounds.
// ---------------------------------------------------------------------------
template <int K>
__global__ __launch_bounds__(256, 2) void k_gemm(
    const float* __restrict__ At,   // [K][Mtot]
    const float* __restrict__ Bt,   // [K][Ntot]
    float* __restrict__ C,          // [Mtot][Ntot]
    int Mtot, int Ntot)
{
    constexpr int BK = 32, STAGES = 3, NT = K / BK;
    constexpr int TILE_FLOATS = BK * 128;          // 4096 floats / operand / stage
    extern __shared__ __align__(16) float smem_dyn[];
    float* sAq = smem_dyn;                         // [STAGES][TILE_FLOATS]
    float* sBq = smem_dyn + STAGES * TILE_FLOATS;
    const int tid = threadIdx.x;
    const int tx  = tid & 15, ty = tid >> 4;
    const int m0  = blockIdx.y * 128;
    const int n0  = blockIdx.x * 128;

    // cp.async mapping: each thread copies four 16B chunks per operand:
    // rows cr, cr+8, cr+16, cr+24 of the BK x 128 tile.
    const int cr = tid >> 5;            // 0..7
    const int cc = (tid & 31) << 2;     // 0,4,...,124
    const uint32_t sA0 = (uint32_t)__cvta_generic_to_shared(sAq);
    const uint32_t sB0 = (uint32_t)__cvta_generic_to_shared(sBq);
    uint32_t so[4];
    #pragma unroll
    for (int i = 0; i < 4; ++i) so[i] = (uint32_t)(((cr + 8 * i) * 128 + cc) * 4);

    unsigned long long acc2[8][4];
    #pragma unroll
    for (int i = 0; i < 8; ++i)
        #pragma unroll
        for (int j = 0; j < 4; ++j) acc2[i][j] = 0ull;

    // prologue: prefetch stages 0,1
    #pragma unroll
    for (int s = 0; s < STAGES - 1; ++s) {
        const size_t gk = (size_t)s * BK;
        #pragma unroll
        for (int i = 0; i < 4; ++i) {
            cp16(sA0 + s * (TILE_FLOATS * 4) + so[i],
                 At + (gk + cr + 8 * i) * (size_t)Mtot + m0 + cc);
            cp16(sB0 + s * (TILE_FLOATS * 4) + so[i],
                 Bt + (gk + cr + 8 * i) * (size_t)Ntot + n0 + cc);
        }
        cp_commit();
    }

    int stage = 0;
    for (int kt = 0; kt < NT; ++kt) {
        cp_wait1();            // oldest in-flight group complete
        __syncthreads();

        if (kt + STAGES - 1 < NT) {
            int ps = (stage + STAGES - 1) % STAGES;
            const size_t gk = (size_t)(kt + STAGES - 1) * BK;
            #pragma unroll
            for (int i = 0; i < 4; ++i) {
                cp16(sA0 + ps * (TILE_FLOATS * 4) + so[i],
                     At + (gk + cr + 8 * i) * (size_t)Mtot + m0 + cc);
                cp16(sB0 + ps * (TILE_FLOATS * 4) + so[i],
                     Bt + (gk + cr + 8 * i) * (size_t)Ntot + n0 + cc);
            }
        }
        cp_commit();           // always commit (possibly empty group)

        const float* a_s = sAq + stage * TILE_FLOATS;
        const float* b_s = sBq + stage * TILE_FLOATS;
        #pragma unroll
        for (int kk = 0; kk < BK; ++kk) {
            float4 a0 = *(const float4*)&a_s[kk * 128 + ty * 8];
            float4 a1 = *(const float4*)&a_s[kk * 128 + ty * 8 + 4];
            ulonglong2 b01 = *(const ulonglong2*)&b_s[kk * 128 + tx * 8];
            ulonglong2 b23 = *(const ulonglong2*)&b_s[kk * 128 + tx * 8 + 4];
            unsigned long long bb[4] = {b01.x, b01.y, b23.x, b23.y};
            float ar[8] = {a0.x, a0.y, a0.z, a0.w, a1.x, a1.y, a1.z, a1.w};
            #pragma unroll
            for (int i = 0; i < 8; ++i) {
                unsigned long long ad = dup2(ar[i]);
                #pragma unroll
                for (int j = 0; j < 4; ++j)
                    ffma2(acc2[i][j], ad, bb[j]);
            }
        }
        stage = (stage + 1) % STAGES;
    }

    #pragma unroll
    for (int i = 0; i < 8; ++i) {
        float* Cr = C + (size_t)(m0 + ty * 8 + i) * Ntot + n0 + tx * 8;
        float2 p0 = unpack2(acc2[i][0]);
        float2 p1 = unpack2(acc2[i][1]);
        float2 p2 = unpack2(acc2[i][2]);
        float2 p3 = unpack2(acc2[i][3]);
        float4 o0, o1;
        o0.x = gelu_f(p0.x); o0.y = gelu_f(p0.y);
        o0.z = gelu_f(p1.x); o0.w = gelu_f(p1.y);
        o1.x = gelu_f(p2.x); o1.y = gelu_f(p2.y);
        o1.z = gelu_f(p3.x); o1.w = gelu_f(p3.y);
        *(float4*)Cr       = o0;
        *(float4*)(Cr + 4) = o1;
    }
}

// ---------------------------------------------------------------------------
// Stage 1+2 fused. Gather-matmul uses adjacent column pairs + FFMA2: thread
// owns proc columns (2tid, 2tid+1) and (2tid+512, 2tid+513). Per-column
// accumulation is still sequential ascending-j fma — bitwise identical.
// ---------------------------------------------------------------------------
__global__ __launch_bounds__(256) void k_stage2(const float* __restrict__ PV) {
    __shared__ float sdata[NIN];
    __shared__ int   sIdx[KIN];
    __shared__ float sVal[KIN];
    __shared__ int   pidx[KPROC];
    __shared__ float pval[KPROC];
    __shared__ float sexp[KPROC];
    __shared__ float sdenom;
    const int t   = blockIdx.x;
    const int tid = threadIdx.x;

    {
        const float4* row = (const float4*)(g_acts1 + (size_t)t * NIN);
        float4 r0 = row[tid];
        float4 r1 = row[tid + 256];
        ((float4*)sdata)[tid]       = r0;
        ((float4*)sdata)[tid + 256] = r1;
    }
    __syncthreads();

    topk_fast<NIN / 256>(sdata, KIN, sIdx, sVal);

    unsigned long long A0 = 0ull, A1 = 0ull;   // col pairs (2tid,2tid+1), (+512)
    #pragma unroll 16
    for (int j = 0; j < KIN; ++j) {            // ascending n (reference order)
        const unsigned long long v = dup2(sVal[j]);
        const float* w = g_Wt + (size_t)sIdx[j] * NPROC;
        unsigned long long w0 = *(const unsigned long long*)(w + 2 * tid);
        unsigned long long w1 = *(const unsigned long long*)(w + 2 * tid + 512);
        ffma2(A0, v, w0);
        ffma2(A1, v, w1);
    }
    __syncthreads();
    {
        float2 p0 = unpack2(A0);
        float2 p1 = unpack2(A1);
        sdata[2 * tid]           = gelu_f(p0.x);
        sdata[2 * tid + 1]       = gelu_f(p0.y);
        sdata[2 * tid + 512]     = gelu_f(p1.x);
        sdata[2 * tid + 513]     = gelu_f(p1.y);
    }
    __syncthreads();

    topk_fast<NPROC / 256>(sdata, KPROC, pidx, pval);
    sort_desc(pval, pidx, KPROC);           // jax top_k output order

    if (tid < KPROC) sexp[tid] = expf(pval[tid] - pval[0]);
    __syncthreads();
    if (tid == 0) {
        float s = 0.f;
        for (int j = 0; j < KPROC; ++j) s += sexp[j];
        sdenom = s;
    }
    __syncthreads();
    const float denom = sdenom;
    if (tid < KPROC) pval[tid] = __fdiv_rn(sexp[tid], denom);
    __syncthreads();

    float acc = 0.f;
    #pragma unroll 16
    for (int j = 0; j < KPROC; ++j)
        acc = fmaf(pval[j], PV[(size_t)pidx[j] * DPV + tid], acc);
    g_aggT[(size_t)tid * TOK + t] = acc;    // transposed (k-major for gemm3)
}

// Stage 3 fused: top-256 of 2048, sort desc, weighted pattern combine with
// adjacent-pair FFMA2 (per-column sequential chain over sorted k — bitwise
// identical) -> out
__global__ __launch_bounds__(256) void k_stage3(const float* __restrict__ OP,
                                                float* __restrict__ out) {
    __shared__ float sdata[NOUT];
    __shared__ int   sidx[KOUT];
    __shared__ float sval[KOUT];
    const int t   = blockIdx.x;
    const int tid = threadIdx.x;
    {
        const float4* row = (const float4*)(g_acts3 + (size_t)t * NOUT);
        float4 r0 = row[tid];
        float4 r1 = row[tid + 256];
        ((float4*)sdata)[tid]       = r0;
        ((float4*)sdata)[tid + 256] = r1;
    }
    __syncthreads();
    topk_fast<NOUT / 256>(sdata, KOUT, sidx, sval);
    sort_desc(sval, sidx, KOUT);            // jax top_k output order

    unsigned long long A = 0ull;            // cols (2tid, 2tid+1)
    #pragma unroll 16
    for (int j = 0; j < KOUT; ++j) {        // sequential over sorted k
        const unsigned long long v = dup2(sval[j]);
        const float* p = OP + (size_t)sidx[j] * DMODEL;
        unsigned long long pw = *(const unsigned long long*)(p + 2 * tid);
        ffma2(A, v, pw);
    }
    float2 o = unpack2(A);
    *(float2*)(out + (size_t)t * DMODEL + 2 * tid) = o;
}

extern "C" void kernel_launch(void* const* d_in, const int* in_sizes, int n_in,
                              void* d_out, int out_size) {
    const float* x   = (const float*)d_in[0];  // [2,1024,512]
    const float* ip  = (const float*)d_in[1];  // [2048,512]
    const float* piw = (const float*)d_in[2];  // [1024,2048]
    const float* pv  = (const float*)d_in[3];  // [1024,256]
    const float* oiw = (const float*)d_in[4];  // [2048,256]
    const float* op  = (const float*)d_in[5];  // [2048,512]
    float* out = (float*)d_out;                // [2,1024,512]

    float* xT   = nullptr; cudaGetSymbolAddress((void**)&xT,   g_xT);
    float* ipT  = nullptr; cudaGetSymbolAddress((void**)&ipT,  g_ipT);
    float* oiwT = nullptr; cudaGetSymbolAddress((void**)&oiwT, g_oiwT);
    float* a1p  = nullptr; cudaGetSymbolAddress((void**)&a1p,  g_acts1);
    float* aggT = nullptr; cudaGetSymbolAddress((void**)&aggT, g_aggT);
    float* a3p  = nullptr; cudaGetSymbolAddress((void**)&a3p,  g_acts3);

    // 3 stages x 2 operands x (32x128) floats = 96 KB dynamic smem
    const int GEMM_SMEM = 3 * 2 * 32 * 128 * 4;
    static bool attr_set = false;
    if (!attr_set) {
        cudaFuncSetAttribute(k_gemm<DMODEL>,
            cudaFuncAttributeMaxDynamicSharedMemorySize, GEMM_SMEM);
        cudaFuncSetAttribute(k_gemm<DPV>,
            cudaFuncAttributeMaxDynamicSharedMemorySize, GEMM_SMEM);
        attr_set = true;
    }

    k_transp_all<<<4608, dim3(32, 8)>>>(x, ip, oiw, piw);
    k_gemm<DMODEL><<<dim3(NIN / 128, TOK / 128), 256, GEMM_SMEM>>>(xT, ipT, a1p, TOK, NIN);
    k_stage2<<<TOK, 256>>>(pv);
    k_gemm<DPV><<<dim3(NOUT / 128, TOK / 128), 256, GEMM_SMEM>>>(aggT, oiwT, a3p, TOK, NOUT);
    k_stage3<<<TOK, 256>>>(op, out);
}